// round 1
// baseline (speedup 1.0000x reference)
#include <cuda_runtime.h>

#define N_UE 8192
#define N_AP 2048
#define KE 3
#define NEDGE (N_UE * KE)

// Scratch (alloc-free rule: __device__ globals)
__device__ float g_ue[N_UE * 2];
__device__ float g_ap[N_AP * 2];
__device__ float g_ea[NEDGE * 2];
__device__ float g_msg[N_UE * 3];

struct C2 { float x, y; };

__device__ __forceinline__ C2 cmul(C2 a, C2 b) {
    return C2{a.x * b.x - a.y * b.y, a.x * b.y + a.y * b.x};
}
__device__ __forceinline__ float lrelu(float v) { return v > 0.f ? v : 0.01f * v; }

// ---------------------------------------------------------------------------
// Generic 2-layer MLP: D -> 128 (leaky_relu) -> 2. One thread per row.
// Hidden activations are consumed on the fly (no hidden array -> no spills).
// ---------------------------------------------------------------------------
template <int D>
__global__ void mlp2_kernel(const float* __restrict__ x, int n,
                            const float* __restrict__ W1, const float* __restrict__ b1,
                            const float* __restrict__ W2, const float* __restrict__ b2,
                            float* __restrict__ out)
{
    int i = blockIdx.x * blockDim.x + threadIdx.x;
    if (i >= n) return;
    float xv[D];
#pragma unroll
    for (int d = 0; d < D; d++) xv[d] = x[i * D + d];
    float o0 = b2[0], o1 = b2[1];
#pragma unroll 4
    for (int k = 0; k < 128; k++) {
        float h = b1[k];
#pragma unroll
        for (int d = 0; d < D; d++) h = fmaf(xv[d], W1[d * 128 + k], h);
        h = lrelu(h);
        o0 = fmaf(h, W2[k * 2 + 0], o0);
        o1 = fmaf(h, W2[k * 2 + 1], o1);
    }
    out[i * 2 + 0] = o0;
    out[i * 2 + 1] = o1;
}

// ---------------------------------------------------------------------------
// Quantum statevector helpers. State: 512 complex amplitudes, SoA in smem.
// Qubit q (0..8) corresponds to bit (8-q) of the flat index (axis-major order
// of the (2,)*9 reference tensor). One warp owns one node's state.
// ---------------------------------------------------------------------------
__device__ __forceinline__ void apply1(float* re, float* im,
                                       C2 u00, C2 u01, C2 u10, C2 u11,
                                       int q, int lane)
{
    int s = 1 << (8 - q);
    int ml = s - 1;
#pragma unroll
    for (int p = lane; p < 256; p += 32) {
        int i0 = ((p & ~ml) << 1) | (p & ml);
        int i1 = i0 | s;
        float a0r = re[i0], a0i = im[i0];
        float a1r = re[i1], a1i = im[i1];
        re[i0] = u00.x * a0r - u00.y * a0i + u01.x * a1r - u01.y * a1i;
        im[i0] = u00.x * a0i + u00.y * a0r + u01.x * a1i + u01.y * a1r;
        re[i1] = u10.x * a0r - u10.y * a0i + u11.x * a1r - u11.y * a1i;
        im[i1] = u10.x * a0i + u10.y * a0r + u11.x * a1i + u11.y * a1r;
    }
    __syncwarp();
}

// Controlled-U: apply U on target t restricted to control bit c == 1.
__device__ __forceinline__ void applyc(float* re, float* im,
                                       C2 u00, C2 u01, C2 u10, C2 u11,
                                       int c, int t, int lane)
{
    int sc = 1 << (8 - c), st = 1 << (8 - t);
    int lo = sc < st ? sc : st;
    int hi = sc < st ? st : sc;
    int mlo = lo - 1, mhi = hi - 1;
#pragma unroll
    for (int p = lane; p < 128; p += 32) {
        int x = ((p & ~mlo) << 1) | (p & mlo);
        x = ((x & ~mhi) << 1) | (x & mhi);
        int i0 = x | sc;       // control=1, target=0
        int i1 = i0 | st;      // control=1, target=1
        float a0r = re[i0], a0i = im[i0];
        float a1r = re[i1], a1i = im[i1];
        re[i0] = u00.x * a0r - u00.y * a0i + u01.x * a1r - u01.y * a1i;
        im[i0] = u00.x * a0i + u00.y * a0r + u01.x * a1i + u01.y * a1r;
        re[i1] = u10.x * a0r - u10.y * a0i + u11.x * a1r - u11.y * a1i;
        im[i1] = u10.x * a0i + u10.y * a0r + u11.x * a1i + u11.y * a1r;
    }
    __syncwarp();
}

// CNOT: swap amplitudes where control=1 between target=0/1.
__device__ __forceinline__ void cxg(float* re, float* im, int c, int t, int lane)
{
    int sc = 1 << (8 - c), st = 1 << (8 - t);
    int lo = sc < st ? sc : st;
    int hi = sc < st ? st : sc;
    int mlo = lo - 1, mhi = hi - 1;
#pragma unroll
    for (int p = lane; p < 128; p += 32) {
        int x = ((p & ~mlo) << 1) | (p & mlo);
        x = ((x & ~mhi) << 1) | (x & mhi);
        int i0 = x | sc;
        int i1 = i0 | st;
        float tr = re[i0]; re[i0] = re[i1]; re[i1] = tr;
        float ti = im[i0]; im[i0] = im[i1]; im[i1] = ti;
    }
    __syncwarp();
}

// ROT(phi,theta,omega) = RZ(omega) @ RY(theta) @ RZ(phi)
__device__ __forceinline__ void rotm(float phi, float th, float om,
                                     C2& u00, C2& u01, C2& u10, C2& u11)
{
    float c, s, cp, sp, cm, sm;
    __sincosf(0.5f * th, &s, &c);
    float ap = 0.5f * (phi + om);
    float am = 0.5f * (phi - om);
    __sincosf(ap, &sp, &cp);
    __sincosf(am, &sm, &cm);
    u00 = C2{ c * cp, -c * sp};   //  c * e^{-i(phi+om)/2}
    u01 = C2{-s * cm, -s * sm};   // -s * e^{+i(phi-om)/2}
    u10 = C2{ s * cm, -s * sm};   //  s * e^{-i(phi-om)/2}
    u11 = C2{ c * cp,  c * sp};   //  c * e^{+i(phi+om)/2}
}

// ---------------------------------------------------------------------------
// Quantum circuit kernel: one warp per UE node, 8 warps / block (32 KB smem).
// ---------------------------------------------------------------------------
__global__ __launch_bounds__(256)
void qcircuit_kernel(const int* __restrict__ edge_src,
                     const float* __restrict__ strong,   // (1,2,2,3) -> 12
                     const float* __restrict__ inits,    // (1,2)     -> 2
                     const float* __restrict__ update)   // (3,2,4,3) -> 72
{
    __shared__ float sre[8 * 512];
    __shared__ float sim[8 * 512];
    int warp = threadIdx.x >> 5;
    int lane = threadIdx.x & 31;
    int n = blockIdx.x * 8 + warp;
    if (n >= N_UE) return;
    float* re = sre + warp * 512;
    float* im = sim + warp * 512;

    // ---- gather the 14 per-node angles -------------------------------------
    // qubit 0..2 : edge features ea[n*3+q]   (RX=a, RZ=b)
    // qubit 3    : ue embedding
    // qubit 4..6 : neighbor ap embeddings ap[edge_src[n*3+i]]
    float a[7], b[7];
#pragma unroll
    for (int q = 0; q < 3; q++) {
        a[q] = g_ea[(n * 3 + q) * 2 + 0];
        b[q] = g_ea[(n * 3 + q) * 2 + 1];
    }
    a[3] = g_ue[n * 2 + 0];
    b[3] = g_ue[n * 2 + 1];
#pragma unroll
    for (int i = 0; i < 3; i++) {
        int src = edge_src[n * 3 + i];
        a[4 + i] = g_ap[src * 2 + 0];
        b[4 + i] = g_ap[src * 2 + 1];
    }

    // ---- initial product state: RZ(b) RX(a) |0> per qubit, qubits 7,8 = |0>
    C2 sq[7][2];
#pragma unroll
    for (int q = 0; q < 7; q++) {
        float ca, sa, cb, sb;
        __sincosf(0.5f * a[q], &sa, &ca);
        __sincosf(0.5f * b[q], &sb, &cb);
        sq[q][0] = C2{ca * cb, -ca * sb};   // cos(a/2) e^{-ib/2}
        sq[q][1] = C2{sa * sb, -sa * cb};   // -i sin(a/2) e^{+ib/2}
    }
    for (int i = lane; i < 512; i += 32) {
        if (i & 3) { re[i] = 0.f; im[i] = 0.f; }
        else {
            C2 v = sq[0][(i >> 8) & 1];
#pragma unroll
            for (int q = 1; q < 7; q++) v = cmul(v, sq[q][(i >> (8 - q)) & 1]);
            re[i] = v.x; im[i] = v.y;
        }
    }
    __syncwarp();

    // ---- per-edge message passing: CRX, CRY, sel(strong, [e, nb]) ----------
    float ci, si, cy, sy;
    __sincosf(0.5f * inits[0], &si, &ci);
    __sincosf(0.5f * inits[1], &sy, &cy);

    for (int i = 0; i < 3; i++) {
        int e = i, nb = 4 + i;
        // CRX: control=nb, target=e
        applyc(re, im, C2{ci, 0.f}, C2{0.f, -si}, C2{0.f, -si}, C2{ci, 0.f}, nb, e, lane);
        // CRY: control=e, target=nb
        applyc(re, im, C2{cy, 0.f}, C2{-sy, 0.f}, C2{sy, 0.f}, C2{cy, 0.f}, e, nb, lane);
        // sel(strong[0], wires=[e, nb]): L=2, M=2, r=1 each layer
        int w2[2] = {e, nb};
        for (int l = 0; l < 2; l++) {
#pragma unroll
            for (int j = 0; j < 2; j++) {
                const float* w = strong + (l * 2 + j) * 3;
                C2 u00, u01, u10, u11;
                rotm(w[0], w[1], w[2], u00, u01, u10, u11);
                apply1(re, im, u00, u01, u10, u11, w2[j], lane);
            }
            cxg(re, im, w2[0], w2[1], lane);
            cxg(re, im, w2[1], w2[0], lane);
        }
    }

    // ---- update: sel(update[i], wires=[3, 4+i, 7, 8]): L=2, M=4 ------------
    for (int i = 0; i < 3; i++) {
        int w4[4] = {3, 4 + i, 7, 8};
        for (int l = 0; l < 2; l++) {
#pragma unroll
            for (int j = 0; j < 4; j++) {
                const float* w = update + ((i * 2 + l) * 4 + j) * 3;
                C2 u00, u01, u10, u11;
                rotm(w[0], w[1], w[2], u00, u01, u10, u11);
                apply1(re, im, u00, u01, u10, u11, w4[j], lane);
            }
            int r = l % 3 + 1;
#pragma unroll
            for (int j = 0; j < 4; j++)
                cxg(re, im, w4[j], w4[(j + r) & 3], lane);
        }
    }

    // ---- <Z> on qubits 3 (bit5), 7 (bit1), 8 (bit0) ------------------------
    float m3 = 0.f, m7 = 0.f, m8 = 0.f;
    for (int i = lane; i < 512; i += 32) {
        float p = re[i] * re[i] + im[i] * im[i];
        m3 += ((i >> 5) & 1) ? -p : p;
        m7 += ((i >> 1) & 1) ? -p : p;
        m8 += (i & 1) ? -p : p;
    }
#pragma unroll
    for (int o = 16; o; o >>= 1) {
        m3 += __shfl_xor_sync(0xFFFFFFFFu, m3, o);
        m7 += __shfl_xor_sync(0xFFFFFFFFu, m7, o);
        m8 += __shfl_xor_sync(0xFFFFFFFFu, m8, o);
    }
    if (lane == 0) {
        g_msg[n * 3 + 0] = m3;
        g_msg[n * 3 + 1] = m7;
        g_msg[n * 3 + 2] = m8;
    }
}

// ---------------------------------------------------------------------------
// Final stage: upd-MLP, residual, LayerNorm(2), 2->128->128->2, sigmoid.
// One warp per node; hidden dims split 4 per lane (d = lane + 32*r).
// ---------------------------------------------------------------------------
__global__ __launch_bounds__(256)
void final_kernel(const float* __restrict__ Wu1, const float* __restrict__ bu1,
                  const float* __restrict__ Wu2, const float* __restrict__ bu2,
                  const float* __restrict__ ln_g, const float* __restrict__ ln_b,
                  const float* __restrict__ Wf1, const float* __restrict__ bf1,
                  const float* __restrict__ Wf2, const float* __restrict__ bf2,
                  const float* __restrict__ Wf3, const float* __restrict__ bf3,
                  float* __restrict__ out)
{
    int gw = (blockIdx.x * blockDim.x + threadIdx.x) >> 5;
    int lane = threadIdx.x & 31;
    if (gw >= N_UE) return;
    int n = gw;

    float in5[5];
    in5[0] = g_ue[n * 2 + 0];
    in5[1] = g_ue[n * 2 + 1];
    in5[2] = g_msg[n * 3 + 0];
    in5[3] = g_msg[n * 3 + 1];
    in5[4] = g_msg[n * 3 + 2];

    // upd = leaky(in5 @ Wu1 + bu1) @ Wu2 + bu2
    float u0 = 0.f, u1 = 0.f;
#pragma unroll
    for (int r = 0; r < 4; r++) {
        int d = lane + 32 * r;
        float h = bu1[d];
#pragma unroll
        for (int k = 0; k < 5; k++) h = fmaf(in5[k], Wu1[k * 128 + d], h);
        h = lrelu(h);
        u0 = fmaf(h, Wu2[d * 2 + 0], u0);
        u1 = fmaf(h, Wu2[d * 2 + 1], u1);
    }
#pragma unroll
    for (int o = 16; o; o >>= 1) {
        u0 += __shfl_xor_sync(0xFFFFFFFFu, u0, o);
        u1 += __shfl_xor_sync(0xFFFFFFFFu, u1, o);
    }
    float h0 = in5[0] + u0 + bu2[0];
    float h1 = in5[1] + u1 + bu2[1];

    // LayerNorm over the 2 features
    float mu = 0.5f * (h0 + h1);
    float d0 = h0 - mu, d1 = h1 - mu;
    float var = 0.5f * (d0 * d0 + d1 * d1);
    float inv = rsqrtf(var + 1e-5f);
    h0 = d0 * inv * ln_g[0] + ln_b[0];
    h1 = d1 * inv * ln_g[1] + ln_b[1];

    // a = leaky(h @ Wf1 + bf1)   (Wf1: [2,128])
    float av[4];
#pragma unroll
    for (int r = 0; r < 4; r++) {
        int d = lane + 32 * r;
        av[r] = lrelu(fmaf(h0, Wf1[d], fmaf(h1, Wf1[128 + d], bf1[d])));
    }

    // b = leaky(a @ Wf2 + bf2)   (Wf2: [128,128], L2-resident broadcast)
    float bv[4];
#pragma unroll
    for (int r = 0; r < 4; r++) bv[r] = bf2[lane + 32 * r];
    for (int k = 0; k < 128; k++) {
        float ak = __shfl_sync(0xFFFFFFFFu, av[k >> 5], k & 31);
        const float* row = Wf2 + k * 128;
#pragma unroll
        for (int r = 0; r < 4; r++) bv[r] = fmaf(ak, __ldg(row + lane + 32 * r), bv[r]);
    }

    // out = sigmoid(leaky(b) @ Wf3 + bf3)   (Wf3: [128,2])
    float o0 = 0.f, o1 = 0.f;
#pragma unroll
    for (int r = 0; r < 4; r++) {
        int d = lane + 32 * r;
        float t = lrelu(bv[r]);
        o0 = fmaf(t, Wf3[d * 2 + 0], o0);
        o1 = fmaf(t, Wf3[d * 2 + 1], o1);
    }
#pragma unroll
    for (int o = 16; o; o >>= 1) {
        o0 += __shfl_xor_sync(0xFFFFFFFFu, o0, o);
        o1 += __shfl_xor_sync(0xFFFFFFFFu, o1, o);
    }
    if (lane == 0) {
        o0 += bf3[0];
        o1 += bf3[1];
        out[n * 2 + 0] = 1.f / (1.f + __expf(-o0));
        out[n * 2 + 1] = 1.f / (1.f + __expf(-o1));
    }
}

// ---------------------------------------------------------------------------
extern "C" void kernel_launch(void* const* d_in, const int* in_sizes, int n_in,
                              void* d_out, int out_size)
{
    (void)in_sizes; (void)n_in; (void)out_size;
    const float* x_ue      = (const float*)d_in[0];
    const float* x_ap      = (const float*)d_in[1];
    const float* edge_attr = (const float*)d_in[2];
    const int*   edge_src  = (const int*)  d_in[3];
    // d_in[4] = edge_dst (unused)
    const float* Wn1u = (const float*)d_in[5];
    const float* bn1u = (const float*)d_in[6];
    const float* Wn2u = (const float*)d_in[7];
    const float* bn2u = (const float*)d_in[8];
    const float* Wn1a = (const float*)d_in[9];
    const float* bn1a = (const float*)d_in[10];
    const float* Wn2a = (const float*)d_in[11];
    const float* bn2a = (const float*)d_in[12];
    const float* We1  = (const float*)d_in[13];
    const float* be1  = (const float*)d_in[14];
    const float* We2  = (const float*)d_in[15];
    const float* be2  = (const float*)d_in[16];
    const float* strong = (const float*)d_in[17];
    const float* inits  = (const float*)d_in[18];
    const float* update = (const float*)d_in[19];
    const float* Wu1  = (const float*)d_in[20];
    const float* bu1  = (const float*)d_in[21];
    const float* Wu2  = (const float*)d_in[22];
    const float* bu2  = (const float*)d_in[23];
    const float* ln_g = (const float*)d_in[24];
    const float* ln_b = (const float*)d_in[25];
    const float* Wf1  = (const float*)d_in[26];
    const float* bf1  = (const float*)d_in[27];
    const float* Wf2  = (const float*)d_in[28];
    const float* bf2  = (const float*)d_in[29];
    const float* Wf3  = (const float*)d_in[30];
    const float* bf3  = (const float*)d_in[31];

    float *p_ue, *p_ap, *p_ea;
    cudaGetSymbolAddress((void**)&p_ue, g_ue);
    cudaGetSymbolAddress((void**)&p_ap, g_ap);
    cudaGetSymbolAddress((void**)&p_ea, g_ea);

    mlp2_kernel<8><<<(N_UE + 127) / 128, 128>>>(x_ue, N_UE, Wn1u, bn1u, Wn2u, bn2u, p_ue);
    mlp2_kernel<8><<<(N_AP + 127) / 128, 128>>>(x_ap, N_AP, Wn1a, bn1a, Wn2a, bn2a, p_ap);
    mlp2_kernel<4><<<(NEDGE + 127) / 128, 128>>>(edge_attr, NEDGE, We1, be1, We2, be2, p_ea);

    qcircuit_kernel<<<N_UE / 8, 256>>>(edge_src, strong, inits, update);

    final_kernel<<<N_UE / 8, 256>>>(Wu1, bu1, Wu2, bu2, ln_g, ln_b,
                                    Wf1, bf1, Wf2, bf2, Wf3, bf3,
                                    (float*)d_out);
}

// round 2
// speedup vs baseline: 3.0030x; 3.0030x over previous
#include <cuda_runtime.h>

#define N_UE 8192
#define N_AP 2048
#define KE 3
#define NEDGE (N_UE * KE)

// Scratch (alloc-free rule: __device__ globals)
__device__ float g_ue[N_UE * 2];
__device__ float g_ap[N_AP * 2];
__device__ float g_ea[NEDGE * 2];
__device__ float g_msg[N_UE * 3];
__device__ float g_mats[30 * 8];   // 30 precomputed 2x2 complex gate matrices

struct C2 { float x, y; };
struct M2 { float ax, ay, bx, by, cx, cy, dx, dy; }; // u00=(ax,ay) u01=(bx,by) u10=(cx,cy) u11=(dx,dy)

__device__ __forceinline__ C2 cmul(C2 a, C2 b) {
    return C2{a.x * b.x - a.y * b.y, a.x * b.y + a.y * b.x};
}
__device__ __forceinline__ float lrelu(float v) { return v > 0.f ? v : 0.01f * v; }

// ---------------------------------------------------------------------------
// MLPs: D -> 128 (leaky_relu) -> 2, one thread per row.
// ---------------------------------------------------------------------------
template <int D>
__global__ void mlp2_kernel(const float* __restrict__ x, int n,
                            const float* __restrict__ W1, const float* __restrict__ b1,
                            const float* __restrict__ W2, const float* __restrict__ b2,
                            float* __restrict__ out)
{
    int i = blockIdx.x * blockDim.x + threadIdx.x;
    if (i >= n) return;
    float xv[D];
#pragma unroll
    for (int d = 0; d < D; d++) xv[d] = x[i * D + d];
    float o0 = b2[0], o1 = b2[1];
#pragma unroll 4
    for (int k = 0; k < 128; k++) {
        float h = b1[k];
#pragma unroll
        for (int d = 0; d < D; d++) h = fmaf(xv[d], W1[d * 128 + k], h);
        h = lrelu(h);
        o0 = fmaf(h, W2[k * 2 + 0], o0);
        o1 = fmaf(h, W2[k * 2 + 1], o1);
    }
    out[i * 2 + 0] = o0;
    out[i * 2 + 1] = o1;
}

// ---------------------------------------------------------------------------
// Precompute the 30 node-independent gate matrices.
// Layout: [0..3] strong sel ROTs (l*2+j); [4] CRX(inits0); [5] CRY(inits1);
//         [6+k] update ROTs, k = (i*2+l)*4+j  (24 mats).
// ---------------------------------------------------------------------------
__device__ __forceinline__ void rot_to(float* o, float phi, float th, float om)
{
    float c, s, cp, sp, cm, sm;
    __sincosf(0.5f * th, &s, &c);
    __sincosf(0.5f * (phi + om), &sp, &cp);
    __sincosf(0.5f * (phi - om), &sm, &cm);
    o[0] =  c * cp; o[1] = -c * sp;   // u00
    o[2] = -s * cm; o[3] = -s * sm;   // u01
    o[4] =  s * cm; o[5] = -s * sm;   // u10
    o[6] =  c * cp; o[7] =  c * sp;   // u11
}

__global__ void mats_kernel(const float* __restrict__ strong,
                            const float* __restrict__ inits,
                            const float* __restrict__ update)
{
    int t = threadIdx.x;
    if (t < 4) {
        const float* w = strong + t * 3;          // (l*2+j)*3
        rot_to(g_mats + t * 8, w[0], w[1], w[2]);
    } else if (t == 4) {
        float c, s; __sincosf(0.5f * inits[0], &s, &c);
        float* o = g_mats + 4 * 8;
        o[0] = c; o[1] = 0; o[2] = 0; o[3] = -s; o[4] = 0; o[5] = -s; o[6] = c; o[7] = 0;
    } else if (t == 5) {
        float c, s; __sincosf(0.5f * inits[1], &s, &c);
        float* o = g_mats + 5 * 8;
        o[0] = c; o[1] = 0; o[2] = -s; o[3] = 0; o[4] = s; o[5] = 0; o[6] = c; o[7] = 0;
    } else if (t < 30) {
        const float* w = update + (t - 6) * 3;
        rot_to(g_mats + t * 8, w[0], w[1], w[2]);
    }
}

// ---------------------------------------------------------------------------
// Register-resident 9-qubit statevector: one warp per node.
// 512 amps = 32 lanes x 16 regs. Bit mapping (custom permutation):
//   lane bits:   q0->L4(16)  q1->L3(8)  q2->L2(4)  q4->L1(2)  q5->L0(1)
//   reg  bits:   q3->R3(8)   q7->R2(4)  q8->R1(2)  q6->R0(1)
// ---------------------------------------------------------------------------
__device__ __forceinline__ M2 ldmat(int idx)
{
    const float4* p = (const float4*)(g_mats + idx * 8);
    float4 u = __ldg(p), v = __ldg(p + 1);
    return M2{u.x, u.y, u.z, u.w, v.x, v.y, v.z, v.w};
}

// single-qubit gate on a LANE bit
__device__ __forceinline__ void g1l(float* sr, float* si, int LM, const M2& m, int lane)
{
    bool hi = (lane & LM) != 0;
    float pax = hi ? m.dx : m.ax, pay = hi ? m.dy : m.ay;  // coeff on own value
    float pbx = hi ? m.cx : m.bx, pby = hi ? m.cy : m.by;  // coeff on partner
#pragma unroll
    for (int r = 0; r < 16; r++) {
        float vr = sr[r], vi = si[r];
        float pr = __shfl_xor_sync(0xFFFFFFFFu, vr, LM);
        float pi = __shfl_xor_sync(0xFFFFFFFFu, vi, LM);
        sr[r] = fmaf(pax, vr, fmaf(-pay, vi, fmaf(pbx, pr, -pby * pi)));
        si[r] = fmaf(pax, vi, fmaf( pay, vr, fmaf(pbx, pi,  pby * pr)));
    }
}

// controlled gate: control LANE bit CM, target LANE bit TM
__device__ __forceinline__ void cg_ll(float* sr, float* si, int CM, int TM, const M2& m, int lane)
{
    bool hi = (lane & TM) != 0;
    bool cb = (lane & CM) != 0;
    float pax = hi ? m.dx : m.ax, pay = hi ? m.dy : m.ay;
    float pbx = hi ? m.cx : m.bx, pby = hi ? m.cy : m.by;
#pragma unroll
    for (int r = 0; r < 16; r++) {
        float vr = sr[r], vi = si[r];
        float pr = __shfl_xor_sync(0xFFFFFFFFu, vr, TM);
        float pi = __shfl_xor_sync(0xFFFFFFFFu, vi, TM);
        float nr = fmaf(pax, vr, fmaf(-pay, vi, fmaf(pbx, pr, -pby * pi)));
        float ni = fmaf(pax, vi, fmaf( pay, vr, fmaf(pbx, pi,  pby * pr)));
        sr[r] = cb ? nr : vr;
        si[r] = cb ? ni : vi;
    }
}

// single-qubit gate on a REG bit
template <int M>
__device__ __forceinline__ void g1r(float* sr, float* si, const M2& m)
{
#pragma unroll
    for (int r = 0; r < 16; r++) {
        if (!(r & M)) {
            int r1 = r | M;
            float a0r = sr[r], a0i = si[r], a1r = sr[r1], a1i = si[r1];
            sr[r]  = fmaf(m.ax, a0r, fmaf(-m.ay, a0i, fmaf(m.bx, a1r, -m.by * a1i)));
            si[r]  = fmaf(m.ax, a0i, fmaf( m.ay, a0r, fmaf(m.bx, a1i,  m.by * a1r)));
            sr[r1] = fmaf(m.cx, a0r, fmaf(-m.cy, a0i, fmaf(m.dx, a1r, -m.dy * a1i)));
            si[r1] = fmaf(m.cx, a0i, fmaf( m.cy, a0r, fmaf(m.dx, a1i,  m.dy * a1r)));
        }
    }
}

// controlled gate: control REG bit CM, target LANE bit TM
template <int CM>
__device__ __forceinline__ void cg_rl(float* sr, float* si, int TM, const M2& m, int lane)
{
    bool hi = (lane & TM) != 0;
    float pax = hi ? m.dx : m.ax, pay = hi ? m.dy : m.ay;
    float pbx = hi ? m.cx : m.bx, pby = hi ? m.cy : m.by;
#pragma unroll
    for (int r = 0; r < 16; r++) {
        if (r & CM) {
            float vr = sr[r], vi = si[r];
            float pr = __shfl_xor_sync(0xFFFFFFFFu, vr, TM);
            float pi = __shfl_xor_sync(0xFFFFFFFFu, vi, TM);
            sr[r] = fmaf(pax, vr, fmaf(-pay, vi, fmaf(pbx, pr, -pby * pi)));
            si[r] = fmaf(pax, vi, fmaf( pay, vr, fmaf(pbx, pi,  pby * pr)));
        }
    }
}

// controlled gate: control LANE bit CM, target REG bit TM
template <int TM>
__device__ __forceinline__ void cg_lr(float* sr, float* si, int CM, const M2& m, int lane)
{
    bool cb = (lane & CM) != 0;
#pragma unroll
    for (int r = 0; r < 16; r++) {
        if (!(r & TM)) {
            int r1 = r | TM;
            float a0r = sr[r], a0i = si[r], a1r = sr[r1], a1i = si[r1];
            float n0r = fmaf(m.ax, a0r, fmaf(-m.ay, a0i, fmaf(m.bx, a1r, -m.by * a1i)));
            float n0i = fmaf(m.ax, a0i, fmaf( m.ay, a0r, fmaf(m.bx, a1i,  m.by * a1r)));
            float n1r = fmaf(m.cx, a0r, fmaf(-m.cy, a0i, fmaf(m.dx, a1r, -m.dy * a1i)));
            float n1i = fmaf(m.cx, a0i, fmaf( m.cy, a0r, fmaf(m.dx, a1i,  m.dy * a1r)));
            sr[r]  = cb ? n0r : a0r;  si[r]  = cb ? n0i : a0i;
            sr[r1] = cb ? n1r : a1r;  si[r1] = cb ? n1i : a1i;
        }
    }
}

// CNOTs
__device__ __forceinline__ void cx_ll(float* sr, float* si, int CM, int TM, int lane)
{
    bool cb = (lane & CM) != 0;
#pragma unroll
    for (int r = 0; r < 16; r++) {
        float pr = __shfl_xor_sync(0xFFFFFFFFu, sr[r], TM);
        float pi = __shfl_xor_sync(0xFFFFFFFFu, si[r], TM);
        sr[r] = cb ? pr : sr[r];
        si[r] = cb ? pi : si[r];
    }
}
template <int CM>
__device__ __forceinline__ void cx_rl(float* sr, float* si, int TM)
{
#pragma unroll
    for (int r = 0; r < 16; r++) {
        if (r & CM) {
            sr[r] = __shfl_xor_sync(0xFFFFFFFFu, sr[r], TM);
            si[r] = __shfl_xor_sync(0xFFFFFFFFu, si[r], TM);
        }
    }
}
template <int TM>
__device__ __forceinline__ void cx_lr(float* sr, float* si, int CM, int lane)
{
    bool cb = (lane & CM) != 0;
#pragma unroll
    for (int r = 0; r < 16; r++) {
        if (!(r & TM)) {
            int r1 = r | TM;
            float t0r = sr[r], t0i = si[r];
            sr[r]  = cb ? sr[r1] : t0r;  si[r]  = cb ? si[r1] : t0i;
            sr[r1] = cb ? t0r : sr[r1];  si[r1] = cb ? t0i : si[r1];
        }
    }
}
template <int CM, int TM>
__device__ __forceinline__ void cx_rr(float* sr, float* si)
{
#pragma unroll
    for (int r = 0; r < 16; r++) {
        if ((r & CM) && !(r & TM)) {
            int r1 = r | TM;
            float t = sr[r]; sr[r] = sr[r1]; sr[r1] = t;
            t = si[r]; si[r] = si[r1]; si[r1] = t;
        }
    }
}

__global__ __launch_bounds__(256)
void qcircuit_kernel(const int* __restrict__ edge_src)
{
    int warp = threadIdx.x >> 5;
    int lane = threadIdx.x & 31;
    int n = blockIdx.x * 8 + warp;

    // ---- gather angles (broadcast loads; every lane the same) --------------
    float a[7], b[7];
#pragma unroll
    for (int q = 0; q < 3; q++) {
        a[q] = __ldg(&g_ea[(n * 3 + q) * 2 + 0]);
        b[q] = __ldg(&g_ea[(n * 3 + q) * 2 + 1]);
    }
    a[3] = __ldg(&g_ue[n * 2 + 0]);
    b[3] = __ldg(&g_ue[n * 2 + 1]);
#pragma unroll
    for (int i = 0; i < 3; i++) {
        int src = __ldg(&edge_src[n * 3 + i]);
        a[4 + i] = __ldg(&g_ap[src * 2 + 0]);
        b[4 + i] = __ldg(&g_ap[src * 2 + 1]);
    }

    // ---- per-qubit init vectors: RZ(b) RX(a) |0> ---------------------------
    C2 sq[7][2];
#pragma unroll
    for (int q = 0; q < 7; q++) {
        float ca, sa, cb2, sb2;
        __sincosf(0.5f * a[q], &sa, &ca);
        __sincosf(0.5f * b[q], &sb2, &cb2);
        sq[q][0] = C2{ca * cb2, -ca * sb2};
        sq[q][1] = C2{sa * sb2, -sa * cb2};
    }

    // lane-determined product of qubits 0,1,2,4,5
    C2 vl = cmul(cmul(cmul(cmul(sq[0][(lane >> 4) & 1], sq[1][(lane >> 3) & 1]),
                           sq[2][(lane >> 2) & 1]), sq[4][(lane >> 1) & 1]),
                 sq[5][lane & 1]);

    float sr[16], si[16];
#pragma unroll
    for (int r = 0; r < 16; r++) { sr[r] = 0.f; si[r] = 0.f; }
    // nonzero regs: q7(R2)=0, q8(R1)=0 -> r in {0,1,8,9}; q3=R3 bit, q6=R0 bit
    {
        C2 v00 = cmul(vl, cmul(sq[3][0], sq[6][0])); sr[0] = v00.x; si[0] = v00.y;
        C2 v01 = cmul(vl, cmul(sq[3][0], sq[6][1])); sr[1] = v01.x; si[1] = v01.y;
        C2 v10 = cmul(vl, cmul(sq[3][1], sq[6][0])); sr[8] = v10.x; si[8] = v10.y;
        C2 v11 = cmul(vl, cmul(sq[3][1], sq[6][1])); sr[9] = v11.x; si[9] = v11.y;
    }

    M2 UX = ldmat(4), UY = ldmat(5);
    M2 S0 = ldmat(0), S1 = ldmat(1), S2 = ldmat(2), S3 = ldmat(3);

    // ---- strong blocks -----------------------------------------------------
    // i=0: e=q0 (L16), nb=q4 (L2)
    cg_ll(sr, si, 2, 16, UX, lane);
    cg_ll(sr, si, 16, 2, UY, lane);
    g1l(sr, si, 16, S0, lane); g1l(sr, si, 2, S1, lane);
    cx_ll(sr, si, 16, 2, lane); cx_ll(sr, si, 2, 16, lane);
    g1l(sr, si, 16, S2, lane); g1l(sr, si, 2, S3, lane);
    cx_ll(sr, si, 16, 2, lane); cx_ll(sr, si, 2, 16, lane);

    // i=1: e=q1 (L8), nb=q5 (L1)
    cg_ll(sr, si, 1, 8, UX, lane);
    cg_ll(sr, si, 8, 1, UY, lane);
    g1l(sr, si, 8, S0, lane); g1l(sr, si, 1, S1, lane);
    cx_ll(sr, si, 8, 1, lane); cx_ll(sr, si, 1, 8, lane);
    g1l(sr, si, 8, S2, lane); g1l(sr, si, 1, S3, lane);
    cx_ll(sr, si, 8, 1, lane); cx_ll(sr, si, 1, 8, lane);

    // i=2: e=q2 (L4), nb=q6 (R1)
    cg_rl<1>(sr, si, 4, UX, lane);          // control q6(reg), target q2(lane)
    cg_lr<1>(sr, si, 4, UY, lane);          // control q2(lane), target q6(reg)
    g1l(sr, si, 4, S0, lane); g1r<1>(sr, si, S1);
    cx_lr<1>(sr, si, 4, lane); cx_rl<1>(sr, si, 4);
    g1l(sr, si, 4, S2, lane); g1r<1>(sr, si, S3);
    cx_lr<1>(sr, si, 4, lane); cx_rl<1>(sr, si, 4);

    // ---- update blocks: wires [q3(R8), q4+i, q7(R4), q8(R2)] ---------------
    // i=0: q4 = L2
    g1r<8>(sr, si, ldmat(6));  g1l(sr, si, 2, ldmat(7), lane);
    g1r<4>(sr, si, ldmat(8));  g1r<2>(sr, si, ldmat(9));
    cx_rl<8>(sr, si, 2); cx_lr<4>(sr, si, 2, lane); cx_rr<4, 2>(sr, si); cx_rr<2, 8>(sr, si);
    g1r<8>(sr, si, ldmat(10)); g1l(sr, si, 2, ldmat(11), lane);
    g1r<4>(sr, si, ldmat(12)); g1r<2>(sr, si, ldmat(13));
    cx_rr<8, 4>(sr, si); cx_lr<2>(sr, si, 2, lane); cx_rr<4, 8>(sr, si); cx_rl<2>(sr, si, 2);

    // i=1: q5 = L1
    g1r<8>(sr, si, ldmat(14)); g1l(sr, si, 1, ldmat(15), lane);
    g1r<4>(sr, si, ldmat(16)); g1r<2>(sr, si, ldmat(17));
    cx_rl<8>(sr, si, 1); cx_lr<4>(sr, si, 1, lane); cx_rr<4, 2>(sr, si); cx_rr<2, 8>(sr, si);
    g1r<8>(sr, si, ldmat(18)); g1l(sr, si, 1, ldmat(19), lane);
    g1r<4>(sr, si, ldmat(20)); g1r<2>(sr, si, ldmat(21));
    cx_rr<8, 4>(sr, si); cx_lr<2>(sr, si, 1, lane); cx_rr<4, 8>(sr, si); cx_rl<2>(sr, si, 1);

    // i=2: q6 = R1  (fully register-local!)
    g1r<8>(sr, si, ldmat(22)); g1r<1>(sr, si, ldmat(23));
    g1r<4>(sr, si, ldmat(24)); g1r<2>(sr, si, ldmat(25));
    cx_rr<8, 1>(sr, si); cx_rr<1, 4>(sr, si); cx_rr<4, 2>(sr, si); cx_rr<2, 8>(sr, si);
    g1r<8>(sr, si, ldmat(26)); g1r<1>(sr, si, ldmat(27));
    g1r<4>(sr, si, ldmat(28)); g1r<2>(sr, si, ldmat(29));
    cx_rr<8, 4>(sr, si); cx_rr<1, 2>(sr, si); cx_rr<4, 8>(sr, si); cx_rr<2, 1>(sr, si);

    // ---- <Z> on q3 (R8), q7 (R4), q8 (R2) ----------------------------------
    float m3 = 0.f, m7 = 0.f, m8 = 0.f;
#pragma unroll
    for (int r = 0; r < 16; r++) {
        float p = fmaf(sr[r], sr[r], si[r] * si[r]);
        m3 += (r & 8) ? -p : p;
        m7 += (r & 4) ? -p : p;
        m8 += (r & 2) ? -p : p;
    }
#pragma unroll
    for (int o = 16; o; o >>= 1) {
        m3 += __shfl_xor_sync(0xFFFFFFFFu, m3, o);
        m7 += __shfl_xor_sync(0xFFFFFFFFu, m7, o);
        m8 += __shfl_xor_sync(0xFFFFFFFFu, m8, o);
    }
    if (lane == 0) {
        g_msg[n * 3 + 0] = m3;
        g_msg[n * 3 + 1] = m7;
        g_msg[n * 3 + 2] = m8;
    }
}

// ---------------------------------------------------------------------------
// Final stage: upd-MLP, residual, LayerNorm(2), 2->128->128->2, sigmoid.
// ---------------------------------------------------------------------------
__global__ __launch_bounds__(256)
void final_kernel(const float* __restrict__ Wu1, const float* __restrict__ bu1,
                  const float* __restrict__ Wu2, const float* __restrict__ bu2,
                  const float* __restrict__ ln_g, const float* __restrict__ ln_b,
                  const float* __restrict__ Wf1, const float* __restrict__ bf1,
                  const float* __restrict__ Wf2, const float* __restrict__ bf2,
                  const float* __restrict__ Wf3, const float* __restrict__ bf3,
                  float* __restrict__ out)
{
    int gw = (blockIdx.x * blockDim.x + threadIdx.x) >> 5;
    int lane = threadIdx.x & 31;
    if (gw >= N_UE) return;
    int n = gw;

    float in5[5];
    in5[0] = g_ue[n * 2 + 0];
    in5[1] = g_ue[n * 2 + 1];
    in5[2] = g_msg[n * 3 + 0];
    in5[3] = g_msg[n * 3 + 1];
    in5[4] = g_msg[n * 3 + 2];

    float u0 = 0.f, u1 = 0.f;
#pragma unroll
    for (int r = 0; r < 4; r++) {
        int d = lane + 32 * r;
        float h = bu1[d];
#pragma unroll
        for (int k = 0; k < 5; k++) h = fmaf(in5[k], Wu1[k * 128 + d], h);
        h = lrelu(h);
        u0 = fmaf(h, Wu2[d * 2 + 0], u0);
        u1 = fmaf(h, Wu2[d * 2 + 1], u1);
    }
#pragma unroll
    for (int o = 16; o; o >>= 1) {
        u0 += __shfl_xor_sync(0xFFFFFFFFu, u0, o);
        u1 += __shfl_xor_sync(0xFFFFFFFFu, u1, o);
    }
    float h0 = in5[0] + u0 + bu2[0];
    float h1 = in5[1] + u1 + bu2[1];

    float mu = 0.5f * (h0 + h1);
    float d0 = h0 - mu, d1 = h1 - mu;
    float var = 0.5f * (d0 * d0 + d1 * d1);
    float inv = rsqrtf(var + 1e-5f);
    h0 = d0 * inv * ln_g[0] + ln_b[0];
    h1 = d1 * inv * ln_g[1] + ln_b[1];

    float av[4];
#pragma unroll
    for (int r = 0; r < 4; r++) {
        int d = lane + 32 * r;
        av[r] = lrelu(fmaf(h0, Wf1[d], fmaf(h1, Wf1[128 + d], bf1[d])));
    }

    float bv[4];
#pragma unroll
    for (int r = 0; r < 4; r++) bv[r] = bf2[lane + 32 * r];
    for (int k = 0; k < 128; k++) {
        float ak = __shfl_sync(0xFFFFFFFFu, av[k >> 5], k & 31);
        const float* row = Wf2 + k * 128;
#pragma unroll
        for (int r = 0; r < 4; r++) bv[r] = fmaf(ak, __ldg(row + lane + 32 * r), bv[r]);
    }

    float o0 = 0.f, o1 = 0.f;
#pragma unroll
    for (int r = 0; r < 4; r++) {
        int d = lane + 32 * r;
        float t = lrelu(bv[r]);
        o0 = fmaf(t, Wf3[d * 2 + 0], o0);
        o1 = fmaf(t, Wf3[d * 2 + 1], o1);
    }
#pragma unroll
    for (int o = 16; o; o >>= 1) {
        o0 += __shfl_xor_sync(0xFFFFFFFFu, o0, o);
        o1 += __shfl_xor_sync(0xFFFFFFFFu, o1, o);
    }
    if (lane == 0) {
        o0 += bf3[0];
        o1 += bf3[1];
        out[n * 2 + 0] = 1.f / (1.f + __expf(-o0));
        out[n * 2 + 1] = 1.f / (1.f + __expf(-o1));
    }
}

// ---------------------------------------------------------------------------
extern "C" void kernel_launch(void* const* d_in, const int* in_sizes, int n_in,
                              void* d_out, int out_size)
{
    (void)in_sizes; (void)n_in; (void)out_size;
    const float* x_ue      = (const float*)d_in[0];
    const float* x_ap      = (const float*)d_in[1];
    const float* edge_attr = (const float*)d_in[2];
    const int*   edge_src  = (const int*)  d_in[3];
    const float* Wn1u = (const float*)d_in[5];
    const float* bn1u = (const float*)d_in[6];
    const float* Wn2u = (const float*)d_in[7];
    const float* bn2u = (const float*)d_in[8];
    const float* Wn1a = (const float*)d_in[9];
    const float* bn1a = (const float*)d_in[10];
    const float* Wn2a = (const float*)d_in[11];
    const float* bn2a = (const float*)d_in[12];
    const float* We1  = (const float*)d_in[13];
    const float* be1  = (const float*)d_in[14];
    const float* We2  = (const float*)d_in[15];
    const float* be2  = (const float*)d_in[16];
    const float* strong = (const float*)d_in[17];
    const float* inits  = (const float*)d_in[18];
    const float* update = (const float*)d_in[19];
    const float* Wu1  = (const float*)d_in[20];
    const float* bu1  = (const float*)d_in[21];
    const float* Wu2  = (const float*)d_in[22];
    const float* bu2  = (const float*)d_in[23];
    const float* ln_g = (const float*)d_in[24];
    const float* ln_b = (const float*)d_in[25];
    const float* Wf1  = (const float*)d_in[26];
    const float* bf1  = (const float*)d_in[27];
    const float* Wf2  = (const float*)d_in[28];
    const float* bf2  = (const float*)d_in[29];
    const float* Wf3  = (const float*)d_in[30];
    const float* bf3  = (const float*)d_in[31];

    float *p_ue, *p_ap, *p_ea;
    cudaGetSymbolAddress((void**)&p_ue, g_ue);
    cudaGetSymbolAddress((void**)&p_ap, g_ap);
    cudaGetSymbolAddress((void**)&p_ea, g_ea);

    mats_kernel<<<1, 32>>>(strong, inits, update);
    mlp2_kernel<8><<<(N_UE + 127) / 128, 128>>>(x_ue, N_UE, Wn1u, bn1u, Wn2u, bn2u, p_ue);
    mlp2_kernel<8><<<(N_AP + 127) / 128, 128>>>(x_ap, N_AP, Wn1a, bn1a, Wn2a, bn2a, p_ap);
    mlp2_kernel<4><<<(NEDGE + 127) / 128, 128>>>(edge_attr, NEDGE, We1, be1, We2, be2, p_ea);

    qcircuit_kernel<<<N_UE / 8, 256>>>(edge_src);

    final_kernel<<<N_UE / 8, 256>>>(Wu1, bu1, Wu2, bu2, ln_g, ln_b,
                                    Wf1, bf1, Wf2, bf2, Wf3, bf3,
                                    (float*)d_out);
}

// round 3
// speedup vs baseline: 5.0845x; 1.6931x over previous
#include <cuda_runtime.h>

#define N_UE 8192
#define N_AP 2048
#define KE 3
#define NEDGE (N_UE * KE)

// Scratch (alloc-free rule: __device__ globals)
__device__ float g_mats[30 * 8];   // update-block ROT matrices (indices 6..29 used)
__device__ float g_mats4[32];      // fused strong-block 4x4 unitary (row-permuted)

struct C2 { float x, y; };
struct M2 { float ax, ay, bx, by, cx, cy, dx, dy; };

__device__ __forceinline__ C2 cmul(C2 a, C2 b) {
    return C2{a.x * b.x - a.y * b.y, a.x * b.y + a.y * b.x};
}
__device__ __forceinline__ float lrelu(float v) { return v > 0.f ? v : 0.01f * v; }

// ---------------------------------------------------------------------------
// mats_kernel: precompute node-independent gate data.
//  - threads 6..29: update ROT 2x2s into g_mats (same layout as before)
//  - thread 0: compose the 10-gate strong block into one 4x4 complex unitary
//    in basis idx = 2*b_e + b_nb, then store ROW-PERMUTED:
//    row rI -> [U[rI][rI], U[rI][rI^2], U[rI][rI^1], U[rI][rI^3]]
//              (own,       e-flip,      nb-flip,     both)
// ---------------------------------------------------------------------------
struct cplx { float r, i; };

__device__ __forceinline__ void rot_to(float* o, float phi, float th, float om)
{
    float c, s, cp, sp, cm, sm;
    __sincosf(0.5f * th, &s, &c);
    __sincosf(0.5f * (phi + om), &sp, &cp);
    __sincosf(0.5f * (phi - om), &sm, &cm);
    o[0] =  c * cp; o[1] = -c * sp;
    o[2] = -s * cm; o[3] = -s * sm;
    o[4] =  s * cm; o[5] = -s * sm;
    o[6] =  c * cp; o[7] =  c * sp;
}

__device__ void rot2c(cplx* o, float phi, float th, float om)
{
    float c, s, cp, sp, cm, sm;
    __sincosf(0.5f * th, &s, &c);
    __sincosf(0.5f * (phi + om), &sp, &cp);
    __sincosf(0.5f * (phi - om), &sm, &cm);
    o[0] = cplx{ c * cp, -c * sp};
    o[1] = cplx{-s * cm, -s * sm};
    o[2] = cplx{ s * cm, -s * sm};
    o[3] = cplx{ c * cp,  c * sp};
}

__device__ void lmul4(cplx* U, const cplx* G)   // U <- G @ U
{
    cplx T[16];
    for (int i = 0; i < 4; i++)
        for (int j = 0; j < 4; j++) {
            cplx s{0.f, 0.f};
            for (int k = 0; k < 4; k++) {
                cplx g = G[i * 4 + k], u = U[k * 4 + j];
                s.r += g.r * u.r - g.i * u.i;
                s.i += g.r * u.i + g.i * u.r;
            }
            T[i * 4 + j] = s;
        }
    for (int i = 0; i < 16; i++) U[i] = T[i];
}

__device__ __forceinline__ void zero16(cplx* G) { for (int i = 0; i < 16; i++) G[i] = cplx{0.f, 0.f}; }

__global__ void mats_kernel(const float* __restrict__ strong,
                            const float* __restrict__ inits,
                            const float* __restrict__ update)
{
    int t = threadIdx.x;
    if (t >= 6 && t < 30)
        rot_to(g_mats + t * 8, update[(t - 6) * 3], update[(t - 6) * 3 + 1], update[(t - 6) * 3 + 2]);

    if (t == 0) {
        cplx U[16], G[16], r2[4];
        zero16(U); U[0] = U[5] = U[10] = U[15] = cplx{1.f, 0.f};

        // G1: CRX (control=nb, target=e), angle inits[0]
        float c, s;
        __sincosf(0.5f * inits[0], &s, &c);
        zero16(G);
        G[0 * 4 + 0] = cplx{1.f, 0.f}; G[2 * 4 + 2] = cplx{1.f, 0.f};
        G[1 * 4 + 1] = cplx{c, 0.f};  G[1 * 4 + 3] = cplx{0.f, -s};
        G[3 * 4 + 1] = cplx{0.f, -s}; G[3 * 4 + 3] = cplx{c, 0.f};
        lmul4(U, G);

        // G2: CRY (control=e, target=nb), angle inits[1]
        __sincosf(0.5f * inits[1], &s, &c);
        zero16(G);
        G[0 * 4 + 0] = cplx{1.f, 0.f}; G[1 * 4 + 1] = cplx{1.f, 0.f};
        G[2 * 4 + 2] = cplx{c, 0.f};  G[2 * 4 + 3] = cplx{-s, 0.f};
        G[3 * 4 + 2] = cplx{s, 0.f};  G[3 * 4 + 3] = cplx{c, 0.f};
        lmul4(U, G);

        for (int l = 0; l < 2; l++) {
            // ROT on e
            rot2c(r2, strong[(l * 2 + 0) * 3], strong[(l * 2 + 0) * 3 + 1], strong[(l * 2 + 0) * 3 + 2]);
            zero16(G);
            G[0 * 4 + 0] = r2[0]; G[0 * 4 + 2] = r2[1]; G[2 * 4 + 0] = r2[2]; G[2 * 4 + 2] = r2[3];
            G[1 * 4 + 1] = r2[0]; G[1 * 4 + 3] = r2[1]; G[3 * 4 + 1] = r2[2]; G[3 * 4 + 3] = r2[3];
            lmul4(U, G);
            // ROT on nb
            rot2c(r2, strong[(l * 2 + 1) * 3], strong[(l * 2 + 1) * 3 + 1], strong[(l * 2 + 1) * 3 + 2]);
            zero16(G);
            G[0 * 4 + 0] = r2[0]; G[0 * 4 + 1] = r2[1]; G[1 * 4 + 0] = r2[2]; G[1 * 4 + 1] = r2[3];
            G[2 * 4 + 2] = r2[0]; G[2 * 4 + 3] = r2[1]; G[3 * 4 + 2] = r2[2]; G[3 * 4 + 3] = r2[3];
            lmul4(U, G);
            // CX (control=e, target=nb): swap idx2<->idx3
            zero16(G);
            G[0 * 4 + 0] = cplx{1.f, 0.f}; G[1 * 4 + 1] = cplx{1.f, 0.f};
            G[2 * 4 + 3] = cplx{1.f, 0.f}; G[3 * 4 + 2] = cplx{1.f, 0.f};
            lmul4(U, G);
            // CX (control=nb, target=e): swap idx1<->idx3
            zero16(G);
            G[0 * 4 + 0] = cplx{1.f, 0.f}; G[2 * 4 + 2] = cplx{1.f, 0.f};
            G[1 * 4 + 3] = cplx{1.f, 0.f}; G[3 * 4 + 1] = cplx{1.f, 0.f};
            lmul4(U, G);
        }

        // store row-permuted
        for (int rI = 0; rI < 4; rI++) {
            int cols[4] = {rI, rI ^ 2, rI ^ 1, rI ^ 3};
            for (int j = 0; j < 4; j++) {
                g_mats4[rI * 8 + j * 2 + 0] = U[rI * 4 + cols[j]].r;
                g_mats4[rI * 8 + j * 2 + 1] = U[rI * 4 + cols[j]].i;
            }
        }
    }
}

// ---------------------------------------------------------------------------
// Register statevector gate primitives (bit mapping):
//   lane bits: q0->L16 q1->L8 q2->L4 q4->L2 q5->L1
//   reg  bits: q3->R8  q7->R4 q8->R2 q6->R1
// ---------------------------------------------------------------------------
__device__ __forceinline__ M2 ldmat(int idx)
{
    const float4* p = (const float4*)(g_mats + idx * 8);
    float4 u = __ldg(p), v = __ldg(p + 1);
    return M2{u.x, u.y, u.z, u.w, v.x, v.y, v.z, v.w};
}

__device__ __forceinline__ void g1l(float* sr, float* si, int LM, const M2& m, int lane)
{
    bool hi = (lane & LM) != 0;
    float pax = hi ? m.dx : m.ax, pay = hi ? m.dy : m.ay;
    float pbx = hi ? m.cx : m.bx, pby = hi ? m.cy : m.by;
#pragma unroll
    for (int r = 0; r < 16; r++) {
        float vr = sr[r], vi = si[r];
        float pr = __shfl_xor_sync(0xFFFFFFFFu, vr, LM);
        float pi = __shfl_xor_sync(0xFFFFFFFFu, vi, LM);
        sr[r] = fmaf(pax, vr, fmaf(-pay, vi, fmaf(pbx, pr, -pby * pi)));
        si[r] = fmaf(pax, vi, fmaf( pay, vr, fmaf(pbx, pi,  pby * pr)));
    }
}

template <int M>
__device__ __forceinline__ void g1r(float* sr, float* si, const M2& m)
{
#pragma unroll
    for (int r = 0; r < 16; r++) {
        if (!(r & M)) {
            int r1 = r | M;
            float a0r = sr[r], a0i = si[r], a1r = sr[r1], a1i = si[r1];
            sr[r]  = fmaf(m.ax, a0r, fmaf(-m.ay, a0i, fmaf(m.bx, a1r, -m.by * a1i)));
            si[r]  = fmaf(m.ax, a0i, fmaf( m.ay, a0r, fmaf(m.bx, a1i,  m.by * a1r)));
            sr[r1] = fmaf(m.cx, a0r, fmaf(-m.cy, a0i, fmaf(m.dx, a1r, -m.dy * a1i)));
            si[r1] = fmaf(m.cx, a0i, fmaf( m.cy, a0r, fmaf(m.dx, a1i,  m.dy * a1r)));
        }
    }
}

template <int CM>
__device__ __forceinline__ void cx_rl(float* sr, float* si, int TM)
{
#pragma unroll
    for (int r = 0; r < 16; r++) {
        if (r & CM) {
            sr[r] = __shfl_xor_sync(0xFFFFFFFFu, sr[r], TM);
            si[r] = __shfl_xor_sync(0xFFFFFFFFu, si[r], TM);
        }
    }
}
template <int TM>
__device__ __forceinline__ void cx_lr(float* sr, float* si, int CM, int lane)
{
    bool cb = (lane & CM) != 0;
#pragma unroll
    for (int r = 0; r < 16; r++) {
        if (!(r & TM)) {
            int r1 = r | TM;
            float t0r = sr[r], t0i = si[r];
            sr[r]  = cb ? sr[r1] : t0r;  si[r]  = cb ? si[r1] : t0i;
            sr[r1] = cb ? t0r : sr[r1];  si[r1] = cb ? t0i : si[r1];
        }
    }
}
template <int CM, int TM>
__device__ __forceinline__ void cx_rr(float* sr, float* si)
{
#pragma unroll
    for (int r = 0; r < 16; r++) {
        if ((r & CM) && !(r & TM)) {
            int r1 = r | TM;
            float t = sr[r]; sr[r] = sr[r1]; sr[r1] = t;
            t = si[r]; si[r] = si[r1]; si[r1] = t;
        }
    }
}

// Fused strong block: both wires on lane bits EM (e), NM (nb).
__device__ __forceinline__ void strong_ll(float* sr, float* si, int EM, int NM, int lane)
{
    int rI = ((lane & EM) ? 2 : 0) | ((lane & NM) ? 1 : 0);
    const float4* p = (const float4*)(g_mats4 + rI * 8);
    float4 u = __ldg(p), v = __ldg(p + 1);   // [own, e-flip] , [nb-flip, both]
#pragma unroll
    for (int r = 0; r < 16; r++) {
        float vr = sr[r], vi = si[r];
        float er = __shfl_xor_sync(0xFFFFFFFFu, vr, EM);
        float ei = __shfl_xor_sync(0xFFFFFFFFu, vi, EM);
        float nr = __shfl_xor_sync(0xFFFFFFFFu, vr, NM);
        float ni = __shfl_xor_sync(0xFFFFFFFFu, vi, NM);
        float br = __shfl_xor_sync(0xFFFFFFFFu, vr, EM | NM);
        float bi = __shfl_xor_sync(0xFFFFFFFFu, vi, EM | NM);
        sr[r] = u.x*vr - u.y*vi + u.z*er - u.w*ei + v.x*nr - v.y*ni + v.z*br - v.w*bi;
        si[r] = u.x*vi + u.y*vr + u.z*ei + u.w*er + v.x*ni + v.y*nr + v.z*bi + v.w*br;
    }
}

// Fused strong block: e on lane bit EM, nb on reg bit R1 (pairs r, r+1).
__device__ __forceinline__ void strong_lr1(float* sr, float* si, int EM, int lane)
{
    int e = (lane & EM) ? 1 : 0;
    const float4* p0 = (const float4*)(g_mats4 + (2 * e) * 8);
    const float4* p1 = (const float4*)(g_mats4 + (2 * e + 1) * 8);
    float4 a0 = __ldg(p0), a1 = __ldg(p0 + 1);
    float4 b0 = __ldg(p1), b1 = __ldg(p1 + 1);
#pragma unroll
    for (int r = 0; r < 16; r += 2) {
        float v0r = sr[r], v0i = si[r], v1r = sr[r + 1], v1i = si[r + 1];
        float e0r = __shfl_xor_sync(0xFFFFFFFFu, v0r, EM);
        float e0i = __shfl_xor_sync(0xFFFFFFFFu, v0i, EM);
        float e1r = __shfl_xor_sync(0xFFFFFFFFu, v1r, EM);
        float e1i = __shfl_xor_sync(0xFFFFFFFFu, v1i, EM);
        // out0 (nb=0): own=v0, e-flip=e0, nb-flip=v1, both=e1
        sr[r]   = a0.x*v0r - a0.y*v0i + a0.z*e0r - a0.w*e0i + a1.x*v1r - a1.y*v1i + a1.z*e1r - a1.w*e1i;
        si[r]   = a0.x*v0i + a0.y*v0r + a0.z*e0i + a0.w*e0r + a1.x*v1i + a1.y*v1r + a1.z*e1i + a1.w*e1r;
        // out1 (nb=1): own=v1, e-flip=e1, nb-flip=v0, both=e0
        sr[r+1] = b0.x*v1r - b0.y*v1i + b0.z*e1r - b0.w*e1i + b1.x*v0r - b1.y*v0i + b1.z*e0r - b1.w*e0i;
        si[r+1] = b0.x*v1i + b0.y*v1r + b0.z*e1i + b0.w*e1r + b1.x*v0i + b1.y*v0r + b1.z*e0i + b1.w*e0r;
    }
}

// ---------------------------------------------------------------------------
// Warp-cooperative MLP row: x (D floats, same for all lanes) -> 2 outputs.
// All lanes return the same result (xor-reduction).
// ---------------------------------------------------------------------------
template <int D>
__device__ __forceinline__ C2 mlp_row(const float* __restrict__ x,
                                      const float* __restrict__ W1, const float* __restrict__ b1,
                                      const float* __restrict__ W2, const float* __restrict__ b2,
                                      int lane)
{
    float xv[D];
#pragma unroll
    for (int d = 0; d < D; d++) xv[d] = __ldg(x + d);
    float o0 = 0.f, o1 = 0.f;
#pragma unroll
    for (int r = 0; r < 4; r++) {
        int d = lane + 32 * r;
        float h = __ldg(b1 + d);
#pragma unroll
        for (int k = 0; k < D; k++) h = fmaf(xv[k], __ldg(W1 + k * 128 + d), h);
        h = lrelu(h);
        float2 w2 = __ldg((const float2*)(W2 + d * 2));
        o0 = fmaf(h, w2.x, o0);
        o1 = fmaf(h, w2.y, o1);
    }
#pragma unroll
    for (int o = 16; o; o >>= 1) {
        o0 += __shfl_xor_sync(0xFFFFFFFFu, o0, o);
        o1 += __shfl_xor_sync(0xFFFFFFFFu, o1, o);
    }
    return C2{o0 + __ldg(b2), o1 + __ldg(b2 + 1)};
}

// ---------------------------------------------------------------------------
// Mega kernel: per-warp = embeddings -> quantum circuit -> classifier head.
// ---------------------------------------------------------------------------
__global__ __launch_bounds__(256)
void mega_kernel(const float* __restrict__ x_ue, const float* __restrict__ x_ap,
                 const float* __restrict__ edge_attr, const int* __restrict__ edge_src,
                 const float* __restrict__ Wn1u, const float* __restrict__ bn1u,
                 const float* __restrict__ Wn2u, const float* __restrict__ bn2u,
                 const float* __restrict__ Wn1a, const float* __restrict__ bn1a,
                 const float* __restrict__ Wn2a, const float* __restrict__ bn2a,
                 const float* __restrict__ We1,  const float* __restrict__ be1,
                 const float* __restrict__ We2,  const float* __restrict__ be2,
                 const float* __restrict__ Wu1,  const float* __restrict__ bu1,
                 const float* __restrict__ Wu2,  const float* __restrict__ bu2,
                 const float* __restrict__ ln_g, const float* __restrict__ ln_b,
                 const float* __restrict__ Wf1,  const float* __restrict__ bf1,
                 const float* __restrict__ Wf2,  const float* __restrict__ bf2,
                 const float* __restrict__ Wf3,  const float* __restrict__ bf3,
                 float* __restrict__ out)
{
    int warp = threadIdx.x >> 5;
    int lane = threadIdx.x & 31;
    int n = blockIdx.x * 8 + warp;

    // ---- Phase 1: embeddings (warp-cooperative MLPs) -----------------------
    float a[7], b[7];
#pragma unroll
    for (int q = 0; q < 3; q++) {
        C2 e = mlp_row<4>(edge_attr + (n * 3 + q) * 4, We1, be1, We2, be2, lane);
        a[q] = e.x; b[q] = e.y;
    }
    {
        C2 u = mlp_row<8>(x_ue + n * 8, Wn1u, bn1u, Wn2u, bn2u, lane);
        a[3] = u.x; b[3] = u.y;
    }
#pragma unroll
    for (int i = 0; i < 3; i++) {
        int src = __ldg(&edge_src[n * 3 + i]);
        C2 p = mlp_row<8>(x_ap + src * 8, Wn1a, bn1a, Wn2a, bn2a, lane);
        a[4 + i] = p.x; b[4 + i] = p.y;
    }

    // ---- Phase 2: quantum circuit ------------------------------------------
    C2 sq[7][2];
#pragma unroll
    for (int q = 0; q < 7; q++) {
        float ca, sa, cb2, sb2;
        __sincosf(0.5f * a[q], &sa, &ca);
        __sincosf(0.5f * b[q], &sb2, &cb2);
        sq[q][0] = C2{ca * cb2, -ca * sb2};
        sq[q][1] = C2{sa * sb2, -sa * cb2};
    }
    C2 vl = cmul(cmul(cmul(cmul(sq[0][(lane >> 4) & 1], sq[1][(lane >> 3) & 1]),
                           sq[2][(lane >> 2) & 1]), sq[4][(lane >> 1) & 1]),
                 sq[5][lane & 1]);

    float sr[16], si[16];
#pragma unroll
    for (int r = 0; r < 16; r++) { sr[r] = 0.f; si[r] = 0.f; }
    {
        C2 v00 = cmul(vl, cmul(sq[3][0], sq[6][0])); sr[0] = v00.x; si[0] = v00.y;
        C2 v01 = cmul(vl, cmul(sq[3][0], sq[6][1])); sr[1] = v01.x; si[1] = v01.y;
        C2 v10 = cmul(vl, cmul(sq[3][1], sq[6][0])); sr[8] = v10.x; si[8] = v10.y;
        C2 v11 = cmul(vl, cmul(sq[3][1], sq[6][1])); sr[9] = v11.x; si[9] = v11.y;
    }

    // fused strong blocks
    strong_ll(sr, si, 16, 2, lane);   // i=0: e=q0(L16), nb=q4(L2)
    strong_ll(sr, si, 8, 1, lane);    // i=1: e=q1(L8),  nb=q5(L1)
    strong_lr1(sr, si, 4, lane);      // i=2: e=q2(L4),  nb=q6(R1)

    // update blocks: wires [q3(R8), q4+i, q7(R4), q8(R2)]
    // i=0: q4 = L2
    g1r<8>(sr, si, ldmat(6));  g1l(sr, si, 2, ldmat(7), lane);
    g1r<4>(sr, si, ldmat(8));  g1r<2>(sr, si, ldmat(9));
    cx_rl<8>(sr, si, 2); cx_lr<4>(sr, si, 2, lane); cx_rr<4, 2>(sr, si); cx_rr<2, 8>(sr, si);
    g1r<8>(sr, si, ldmat(10)); g1l(sr, si, 2, ldmat(11), lane);
    g1r<4>(sr, si, ldmat(12)); g1r<2>(sr, si, ldmat(13));
    cx_rr<8, 4>(sr, si); cx_lr<2>(sr, si, 2, lane); cx_rr<4, 8>(sr, si); cx_rl<2>(sr, si, 2);

    // i=1: q5 = L1
    g1r<8>(sr, si, ldmat(14)); g1l(sr, si, 1, ldmat(15), lane);
    g1r<4>(sr, si, ldmat(16)); g1r<2>(sr, si, ldmat(17));
    cx_rl<8>(sr, si, 1); cx_lr<4>(sr, si, 1, lane); cx_rr<4, 2>(sr, si); cx_rr<2, 8>(sr, si);
    g1r<8>(sr, si, ldmat(18)); g1l(sr, si, 1, ldmat(19), lane);
    g1r<4>(sr, si, ldmat(20)); g1r<2>(sr, si, ldmat(21));
    cx_rr<8, 4>(sr, si); cx_lr<2>(sr, si, 1, lane); cx_rr<4, 8>(sr, si); cx_rl<2>(sr, si, 1);

    // i=2: q6 = R1 (fully register-local)
    g1r<8>(sr, si, ldmat(22)); g1r<1>(sr, si, ldmat(23));
    g1r<4>(sr, si, ldmat(24)); g1r<2>(sr, si, ldmat(25));
    cx_rr<8, 1>(sr, si); cx_rr<1, 4>(sr, si); cx_rr<4, 2>(sr, si); cx_rr<2, 8>(sr, si);
    g1r<8>(sr, si, ldmat(26)); g1r<1>(sr, si, ldmat(27));
    g1r<4>(sr, si, ldmat(28)); g1r<2>(sr, si, ldmat(29));
    cx_rr<8, 4>(sr, si); cx_rr<1, 2>(sr, si); cx_rr<4, 8>(sr, si); cx_rr<2, 1>(sr, si);

    // measurements <Z> on q3(R8), q7(R4), q8(R2)
    float m3 = 0.f, m7 = 0.f, m8 = 0.f;
#pragma unroll
    for (int r = 0; r < 16; r++) {
        float p = fmaf(sr[r], sr[r], si[r] * si[r]);
        m3 += (r & 8) ? -p : p;
        m7 += (r & 4) ? -p : p;
        m8 += (r & 2) ? -p : p;
    }
#pragma unroll
    for (int o = 16; o; o >>= 1) {
        m3 += __shfl_xor_sync(0xFFFFFFFFu, m3, o);
        m7 += __shfl_xor_sync(0xFFFFFFFFu, m7, o);
        m8 += __shfl_xor_sync(0xFFFFFFFFu, m8, o);
    }

    // ---- Phase 3: classifier head ------------------------------------------
    float in5[5] = {a[3], b[3], m3, m7, m8};

    float u0 = 0.f, u1 = 0.f;
#pragma unroll
    for (int r = 0; r < 4; r++) {
        int d = lane + 32 * r;
        float h = __ldg(bu1 + d);
#pragma unroll
        for (int k = 0; k < 5; k++) h = fmaf(in5[k], __ldg(Wu1 + k * 128 + d), h);
        h = lrelu(h);
        float2 w2 = __ldg((const float2*)(Wu2 + d * 2));
        u0 = fmaf(h, w2.x, u0);
        u1 = fmaf(h, w2.y, u1);
    }
#pragma unroll
    for (int o = 16; o; o >>= 1) {
        u0 += __shfl_xor_sync(0xFFFFFFFFu, u0, o);
        u1 += __shfl_xor_sync(0xFFFFFFFFu, u1, o);
    }
    float h0 = in5[0] + u0 + __ldg(bu2);
    float h1 = in5[1] + u1 + __ldg(bu2 + 1);

    float mu = 0.5f * (h0 + h1);
    float d0 = h0 - mu, d1 = h1 - mu;
    float var = 0.5f * (d0 * d0 + d1 * d1);
    float inv = rsqrtf(var + 1e-5f);
    h0 = d0 * inv * __ldg(ln_g) + __ldg(ln_b);
    h1 = d1 * inv * __ldg(ln_g + 1) + __ldg(ln_b + 1);

    float av[4];
#pragma unroll
    for (int r = 0; r < 4; r++) {
        int d = lane + 32 * r;
        av[r] = lrelu(fmaf(h0, __ldg(Wf1 + d), fmaf(h1, __ldg(Wf1 + 128 + d), __ldg(bf1 + d))));
    }

    float bv[4];
#pragma unroll
    for (int r = 0; r < 4; r++) bv[r] = __ldg(bf2 + lane + 32 * r);
    for (int k = 0; k < 128; k++) {
        float ak = __shfl_sync(0xFFFFFFFFu, av[k >> 5], k & 31);
        const float* row = Wf2 + k * 128;
#pragma unroll
        for (int r = 0; r < 4; r++) bv[r] = fmaf(ak, __ldg(row + lane + 32 * r), bv[r]);
    }

    float o0 = 0.f, o1 = 0.f;
#pragma unroll
    for (int r = 0; r < 4; r++) {
        int d = lane + 32 * r;
        float t = lrelu(bv[r]);
        float2 w3 = __ldg((const float2*)(Wf3 + d * 2));
        o0 = fmaf(t, w3.x, o0);
        o1 = fmaf(t, w3.y, o1);
    }
#pragma unroll
    for (int o = 16; o; o >>= 1) {
        o0 += __shfl_xor_sync(0xFFFFFFFFu, o0, o);
        o1 += __shfl_xor_sync(0xFFFFFFFFu, o1, o);
    }
    if (lane == 0) {
        o0 += __ldg(bf3);
        o1 += __ldg(bf3 + 1);
        out[n * 2 + 0] = 1.f / (1.f + __expf(-o0));
        out[n * 2 + 1] = 1.f / (1.f + __expf(-o1));
    }
}

// ---------------------------------------------------------------------------
extern "C" void kernel_launch(void* const* d_in, const int* in_sizes, int n_in,
                              void* d_out, int out_size)
{
    (void)in_sizes; (void)n_in; (void)out_size;
    const float* x_ue      = (const float*)d_in[0];
    const float* x_ap      = (const float*)d_in[1];
    const float* edge_attr = (const float*)d_in[2];
    const int*   edge_src  = (const int*)  d_in[3];
    const float* Wn1u = (const float*)d_in[5];
    const float* bn1u = (const float*)d_in[6];
    const float* Wn2u = (const float*)d_in[7];
    const float* bn2u = (const float*)d_in[8];
    const float* Wn1a = (const float*)d_in[9];
    const float* bn1a = (const float*)d_in[10];
    const float* Wn2a = (const float*)d_in[11];
    const float* bn2a = (const float*)d_in[12];
    const float* We1  = (const float*)d_in[13];
    const float* be1  = (const float*)d_in[14];
    const float* We2  = (const float*)d_in[15];
    const float* be2  = (const float*)d_in[16];
    const float* strong = (const float*)d_in[17];
    const float* inits  = (const float*)d_in[18];
    const float* update = (const float*)d_in[19];
    const float* Wu1  = (const float*)d_in[20];
    const float* bu1  = (const float*)d_in[21];
    const float* Wu2  = (const float*)d_in[22];
    const float* bu2  = (const float*)d_in[23];
    const float* ln_g = (const float*)d_in[24];
    const float* ln_b = (const float*)d_in[25];
    const float* Wf1  = (const float*)d_in[26];
    const float* bf1  = (const float*)d_in[27];
    const float* Wf2  = (const float*)d_in[28];
    const float* bf2  = (const float*)d_in[29];
    const float* Wf3  = (const float*)d_in[30];
    const float* bf3  = (const float*)d_in[31];

    mats_kernel<<<1, 32>>>(strong, inits, update);

    mega_kernel<<<N_UE / 8, 256>>>(x_ue, x_ap, edge_attr, edge_src,
                                   Wn1u, bn1u, Wn2u, bn2u,
                                   Wn1a, bn1a, Wn2a, bn2a,
                                   We1, be1, We2, be2,
                                   Wu1, bu1, Wu2, bu2,
                                   ln_g, ln_b, Wf1, bf1, Wf2, bf2, Wf3, bf3,
                                   (float*)d_out);
}

// round 4
// speedup vs baseline: 5.1081x; 1.0046x over previous
#include <cuda_runtime.h>

#define N_UE 8192
#define N_AP 2048
#define KE 3
#define NEDGE (N_UE * KE)

// Scratch (alloc-free rule: __device__ globals)
__device__ float g_mats[30 * 8];   // update-block ROT matrices (indices 6..29 used)
__device__ float g_mats4[32];      // fused strong-block 4x4 unitary (row-permuted)

struct C2 { float x, y; };
struct M2 { float ax, ay, bx, by, cx, cy, dx, dy; };

__device__ __forceinline__ C2 cmul(C2 a, C2 b) {
    return C2{a.x * b.x - a.y * b.y, a.x * b.y + a.y * b.x};
}
__device__ __forceinline__ float lrelu(float v) { return v > 0.f ? v : 0.01f * v; }

// ---------------------------------------------------------------------------
// mats_kernel: precompute node-independent gate data.
//  - threads 6..29: update ROT 2x2s into g_mats (same layout as before)
//  - thread 0: compose the 10-gate strong block into one 4x4 complex unitary
//    in basis idx = 2*b_e + b_nb, then store ROW-PERMUTED:
//    row rI -> [U[rI][rI], U[rI][rI^2], U[rI][rI^1], U[rI][rI^3]]
//              (own,       e-flip,      nb-flip,     both)
// ---------------------------------------------------------------------------
struct cplx { float r, i; };

__device__ __forceinline__ void rot_to(float* o, float phi, float th, float om)
{
    float c, s, cp, sp, cm, sm;
    __sincosf(0.5f * th, &s, &c);
    __sincosf(0.5f * (phi + om), &sp, &cp);
    __sincosf(0.5f * (phi - om), &sm, &cm);
    o[0] =  c * cp; o[1] = -c * sp;
    o[2] = -s * cm; o[3] = -s * sm;
    o[4] =  s * cm; o[5] = -s * sm;
    o[6] =  c * cp; o[7] =  c * sp;
}

__device__ void rot2c(cplx* o, float phi, float th, float om)
{
    float c, s, cp, sp, cm, sm;
    __sincosf(0.5f * th, &s, &c);
    __sincosf(0.5f * (phi + om), &sp, &cp);
    __sincosf(0.5f * (phi - om), &sm, &cm);
    o[0] = cplx{ c * cp, -c * sp};
    o[1] = cplx{-s * cm, -s * sm};
    o[2] = cplx{ s * cm, -s * sm};
    o[3] = cplx{ c * cp,  c * sp};
}

__device__ void lmul4(cplx* U, const cplx* G)   // U <- G @ U
{
    cplx T[16];
    for (int i = 0; i < 4; i++)
        for (int j = 0; j < 4; j++) {
            cplx s{0.f, 0.f};
            for (int k = 0; k < 4; k++) {
                cplx g = G[i * 4 + k], u = U[k * 4 + j];
                s.r += g.r * u.r - g.i * u.i;
                s.i += g.r * u.i + g.i * u.r;
            }
            T[i * 4 + j] = s;
        }
    for (int i = 0; i < 16; i++) U[i] = T[i];
}

__device__ __forceinline__ void zero16(cplx* G) { for (int i = 0; i < 16; i++) G[i] = cplx{0.f, 0.f}; }

__global__ void mats_kernel(const float* __restrict__ strong,
                            const float* __restrict__ inits,
                            const float* __restrict__ update)
{
    int t = threadIdx.x;
    if (t >= 6 && t < 30)
        rot_to(g_mats + t * 8, update[(t - 6) * 3], update[(t - 6) * 3 + 1], update[(t - 6) * 3 + 2]);

    if (t == 0) {
        cplx U[16], G[16], r2[4];
        zero16(U); U[0] = U[5] = U[10] = U[15] = cplx{1.f, 0.f};

        // G1: CRX (control=nb, target=e), angle inits[0]
        float c, s;
        __sincosf(0.5f * inits[0], &s, &c);
        zero16(G);
        G[0 * 4 + 0] = cplx{1.f, 0.f}; G[2 * 4 + 2] = cplx{1.f, 0.f};
        G[1 * 4 + 1] = cplx{c, 0.f};  G[1 * 4 + 3] = cplx{0.f, -s};
        G[3 * 4 + 1] = cplx{0.f, -s}; G[3 * 4 + 3] = cplx{c, 0.f};
        lmul4(U, G);

        // G2: CRY (control=e, target=nb), angle inits[1]
        __sincosf(0.5f * inits[1], &s, &c);
        zero16(G);
        G[0 * 4 + 0] = cplx{1.f, 0.f}; G[1 * 4 + 1] = cplx{1.f, 0.f};
        G[2 * 4 + 2] = cplx{c, 0.f};  G[2 * 4 + 3] = cplx{-s, 0.f};
        G[3 * 4 + 2] = cplx{s, 0.f};  G[3 * 4 + 3] = cplx{c, 0.f};
        lmul4(U, G);

        for (int l = 0; l < 2; l++) {
            // ROT on e
            rot2c(r2, strong[(l * 2 + 0) * 3], strong[(l * 2 + 0) * 3 + 1], strong[(l * 2 + 0) * 3 + 2]);
            zero16(G);
            G[0 * 4 + 0] = r2[0]; G[0 * 4 + 2] = r2[1]; G[2 * 4 + 0] = r2[2]; G[2 * 4 + 2] = r2[3];
            G[1 * 4 + 1] = r2[0]; G[1 * 4 + 3] = r2[1]; G[3 * 4 + 1] = r2[2]; G[3 * 4 + 3] = r2[3];
            lmul4(U, G);
            // ROT on nb
            rot2c(r2, strong[(l * 2 + 1) * 3], strong[(l * 2 + 1) * 3 + 1], strong[(l * 2 + 1) * 3 + 2]);
            zero16(G);
            G[0 * 4 + 0] = r2[0]; G[0 * 4 + 1] = r2[1]; G[1 * 4 + 0] = r2[2]; G[1 * 4 + 1] = r2[3];
            G[2 * 4 + 2] = r2[0]; G[2 * 4 + 3] = r2[1]; G[3 * 4 + 2] = r2[2]; G[3 * 4 + 3] = r2[3];
            lmul4(U, G);
            // CX (control=e, target=nb): swap idx2<->idx3
            zero16(G);
            G[0 * 4 + 0] = cplx{1.f, 0.f}; G[1 * 4 + 1] = cplx{1.f, 0.f};
            G[2 * 4 + 3] = cplx{1.f, 0.f}; G[3 * 4 + 2] = cplx{1.f, 0.f};
            lmul4(U, G);
            // CX (control=nb, target=e): swap idx1<->idx3
            zero16(G);
            G[0 * 4 + 0] = cplx{1.f, 0.f}; G[2 * 4 + 2] = cplx{1.f, 0.f};
            G[1 * 4 + 3] = cplx{1.f, 0.f}; G[3 * 4 + 1] = cplx{1.f, 0.f};
            lmul4(U, G);
        }

        // store row-permuted
        for (int rI = 0; rI < 4; rI++) {
            int cols[4] = {rI, rI ^ 2, rI ^ 1, rI ^ 3};
            for (int j = 0; j < 4; j++) {
                g_mats4[rI * 8 + j * 2 + 0] = U[rI * 4 + cols[j]].r;
                g_mats4[rI * 8 + j * 2 + 1] = U[rI * 4 + cols[j]].i;
            }
        }
    }
}

// ---------------------------------------------------------------------------
// Register statevector gate primitives (bit mapping):
//   lane bits: q0->L16 q1->L8 q2->L4 q4->L2 q5->L1
//   reg  bits: q3->R8  q7->R4 q8->R2 q6->R1
// ---------------------------------------------------------------------------
__device__ __forceinline__ M2 ldmat(int idx)
{
    const float4* p = (const float4*)(g_mats + idx * 8);
    float4 u = __ldg(p), v = __ldg(p + 1);
    return M2{u.x, u.y, u.z, u.w, v.x, v.y, v.z, v.w};
}

__device__ __forceinline__ void g1l(float* sr, float* si, int LM, const M2& m, int lane)
{
    bool hi = (lane & LM) != 0;
    float pax = hi ? m.dx : m.ax, pay = hi ? m.dy : m.ay;
    float pbx = hi ? m.cx : m.bx, pby = hi ? m.cy : m.by;
#pragma unroll
    for (int r = 0; r < 16; r++) {
        float vr = sr[r], vi = si[r];
        float pr = __shfl_xor_sync(0xFFFFFFFFu, vr, LM);
        float pi = __shfl_xor_sync(0xFFFFFFFFu, vi, LM);
        sr[r] = fmaf(pax, vr, fmaf(-pay, vi, fmaf(pbx, pr, -pby * pi)));
        si[r] = fmaf(pax, vi, fmaf( pay, vr, fmaf(pbx, pi,  pby * pr)));
    }
}

template <int M>
__device__ __forceinline__ void g1r(float* sr, float* si, const M2& m)
{
#pragma unroll
    for (int r = 0; r < 16; r++) {
        if (!(r & M)) {
            int r1 = r | M;
            float a0r = sr[r], a0i = si[r], a1r = sr[r1], a1i = si[r1];
            sr[r]  = fmaf(m.ax, a0r, fmaf(-m.ay, a0i, fmaf(m.bx, a1r, -m.by * a1i)));
            si[r]  = fmaf(m.ax, a0i, fmaf( m.ay, a0r, fmaf(m.bx, a1i,  m.by * a1r)));
            sr[r1] = fmaf(m.cx, a0r, fmaf(-m.cy, a0i, fmaf(m.dx, a1r, -m.dy * a1i)));
            si[r1] = fmaf(m.cx, a0i, fmaf( m.cy, a0r, fmaf(m.dx, a1i,  m.dy * a1r)));
        }
    }
}

template <int CM>
__device__ __forceinline__ void cx_rl(float* sr, float* si, int TM)
{
#pragma unroll
    for (int r = 0; r < 16; r++) {
        if (r & CM) {
            sr[r] = __shfl_xor_sync(0xFFFFFFFFu, sr[r], TM);
            si[r] = __shfl_xor_sync(0xFFFFFFFFu, si[r], TM);
        }
    }
}
template <int TM>
__device__ __forceinline__ void cx_lr(float* sr, float* si, int CM, int lane)
{
    bool cb = (lane & CM) != 0;
#pragma unroll
    for (int r = 0; r < 16; r++) {
        if (!(r & TM)) {
            int r1 = r | TM;
            float t0r = sr[r], t0i = si[r];
            sr[r]  = cb ? sr[r1] : t0r;  si[r]  = cb ? si[r1] : t0i;
            sr[r1] = cb ? t0r : sr[r1];  si[r1] = cb ? t0i : si[r1];
        }
    }
}
template <int CM, int TM>
__device__ __forceinline__ void cx_rr(float* sr, float* si)
{
#pragma unroll
    for (int r = 0; r < 16; r++) {
        if ((r & CM) && !(r & TM)) {
            int r1 = r | TM;
            float t = sr[r]; sr[r] = sr[r1]; sr[r1] = t;
            t = si[r]; si[r] = si[r1]; si[r1] = t;
        }
    }
}

// Fused strong block: both wires on lane bits EM (e), NM (nb).
__device__ __forceinline__ void strong_ll(float* sr, float* si, int EM, int NM, int lane)
{
    int rI = ((lane & EM) ? 2 : 0) | ((lane & NM) ? 1 : 0);
    const float4* p = (const float4*)(g_mats4 + rI * 8);
    float4 u = __ldg(p), v = __ldg(p + 1);   // [own, e-flip] , [nb-flip, both]
#pragma unroll
    for (int r = 0; r < 16; r++) {
        float vr = sr[r], vi = si[r];
        float er = __shfl_xor_sync(0xFFFFFFFFu, vr, EM);
        float ei = __shfl_xor_sync(0xFFFFFFFFu, vi, EM);
        float nr = __shfl_xor_sync(0xFFFFFFFFu, vr, NM);
        float ni = __shfl_xor_sync(0xFFFFFFFFu, vi, NM);
        float br = __shfl_xor_sync(0xFFFFFFFFu, vr, EM | NM);
        float bi = __shfl_xor_sync(0xFFFFFFFFu, vi, EM | NM);
        sr[r] = u.x*vr - u.y*vi + u.z*er - u.w*ei + v.x*nr - v.y*ni + v.z*br - v.w*bi;
        si[r] = u.x*vi + u.y*vr + u.z*ei + u.w*er + v.x*ni + v.y*nr + v.z*bi + v.w*br;
    }
}

// Fused strong block: e on lane bit EM, nb on reg bit R1 (pairs r, r+1).
__device__ __forceinline__ void strong_lr1(float* sr, float* si, int EM, int lane)
{
    int e = (lane & EM) ? 1 : 0;
    const float4* p0 = (const float4*)(g_mats4 + (2 * e) * 8);
    const float4* p1 = (const float4*)(g_mats4 + (2 * e + 1) * 8);
    float4 a0 = __ldg(p0), a1 = __ldg(p0 + 1);
    float4 b0 = __ldg(p1), b1 = __ldg(p1 + 1);
#pragma unroll
    for (int r = 0; r < 16; r += 2) {
        float v0r = sr[r], v0i = si[r], v1r = sr[r + 1], v1i = si[r + 1];
        float e0r = __shfl_xor_sync(0xFFFFFFFFu, v0r, EM);
        float e0i = __shfl_xor_sync(0xFFFFFFFFu, v0i, EM);
        float e1r = __shfl_xor_sync(0xFFFFFFFFu, v1r, EM);
        float e1i = __shfl_xor_sync(0xFFFFFFFFu, v1i, EM);
        // out0 (nb=0): own=v0, e-flip=e0, nb-flip=v1, both=e1
        sr[r]   = a0.x*v0r - a0.y*v0i + a0.z*e0r - a0.w*e0i + a1.x*v1r - a1.y*v1i + a1.z*e1r - a1.w*e1i;
        si[r]   = a0.x*v0i + a0.y*v0r + a0.z*e0i + a0.w*e0r + a1.x*v1i + a1.y*v1r + a1.z*e1i + a1.w*e1r;
        // out1 (nb=1): own=v1, e-flip=e1, nb-flip=v0, both=e0
        sr[r+1] = b0.x*v1r - b0.y*v1i + b0.z*e1r - b0.w*e1i + b1.x*v0r - b1.y*v0i + b1.z*e0r - b1.w*e0i;
        si[r+1] = b0.x*v1i + b0.y*v1r + b0.z*e1i + b0.w*e1r + b1.x*v0i + b1.y*v0r + b1.z*e0i + b1.w*e0r;
    }
}

// ---------------------------------------------------------------------------
// Warp-cooperative MLP row: x (D floats, same for all lanes) -> 2 outputs.
// All lanes return the same result (xor-reduction).
// ---------------------------------------------------------------------------
template <int D>
__device__ __forceinline__ C2 mlp_row(const float* __restrict__ x,
                                      const float* __restrict__ W1, const float* __restrict__ b1,
                                      const float* __restrict__ W2, const float* __restrict__ b2,
                                      int lane)
{
    float xv[D];
#pragma unroll
    for (int d = 0; d < D; d++) xv[d] = __ldg(x + d);
    float o0 = 0.f, o1 = 0.f;
#pragma unroll
    for (int r = 0; r < 4; r++) {
        int d = lane + 32 * r;
        float h = __ldg(b1 + d);
#pragma unroll
        for (int k = 0; k < D; k++) h = fmaf(xv[k], __ldg(W1 + k * 128 + d), h);
        h = lrelu(h);
        float2 w2 = __ldg((const float2*)(W2 + d * 2));
        o0 = fmaf(h, w2.x, o0);
        o1 = fmaf(h, w2.y, o1);
    }
#pragma unroll
    for (int o = 16; o; o >>= 1) {
        o0 += __shfl_xor_sync(0xFFFFFFFFu, o0, o);
        o1 += __shfl_xor_sync(0xFFFFFFFFu, o1, o);
    }
    return C2{o0 + __ldg(b2), o1 + __ldg(b2 + 1)};
}

// ---------------------------------------------------------------------------
// Mega kernel: per-warp = embeddings -> quantum circuit -> classifier head.
// ---------------------------------------------------------------------------
__global__ __launch_bounds__(256)
void mega_kernel(const float* __restrict__ x_ue, const float* __restrict__ x_ap,
                 const float* __restrict__ edge_attr, const int* __restrict__ edge_src,
                 const float* __restrict__ Wn1u, const float* __restrict__ bn1u,
                 const float* __restrict__ Wn2u, const float* __restrict__ bn2u,
                 const float* __restrict__ Wn1a, const float* __restrict__ bn1a,
                 const float* __restrict__ Wn2a, const float* __restrict__ bn2a,
                 const float* __restrict__ We1,  const float* __restrict__ be1,
                 const float* __restrict__ We2,  const float* __restrict__ be2,
                 const float* __restrict__ Wu1,  const float* __restrict__ bu1,
                 const float* __restrict__ Wu2,  const float* __restrict__ bu2,
                 const float* __restrict__ ln_g, const float* __restrict__ ln_b,
                 const float* __restrict__ Wf1,  const float* __restrict__ bf1,
                 const float* __restrict__ Wf2,  const float* __restrict__ bf2,
                 const float* __restrict__ Wf3,  const float* __restrict__ bf3,
                 float* __restrict__ out)
{
    int warp = threadIdx.x >> 5;
    int lane = threadIdx.x & 31;
    int n = blockIdx.x * 8 + warp;

    // ---- Phase 1: embeddings (warp-cooperative MLPs) -----------------------
    float a[7], b[7];
#pragma unroll
    for (int q = 0; q < 3; q++) {
        C2 e = mlp_row<4>(edge_attr + (n * 3 + q) * 4, We1, be1, We2, be2, lane);
        a[q] = e.x; b[q] = e.y;
    }
    {
        C2 u = mlp_row<8>(x_ue + n * 8, Wn1u, bn1u, Wn2u, bn2u, lane);
        a[3] = u.x; b[3] = u.y;
    }
#pragma unroll
    for (int i = 0; i < 3; i++) {
        int src = __ldg(&edge_src[n * 3 + i]);
        C2 p = mlp_row<8>(x_ap + src * 8, Wn1a, bn1a, Wn2a, bn2a, lane);
        a[4 + i] = p.x; b[4 + i] = p.y;
    }

    // ---- Phase 2: quantum circuit ------------------------------------------
    C2 sq[7][2];
#pragma unroll
    for (int q = 0; q < 7; q++) {
        float ca, sa, cb2, sb2;
        __sincosf(0.5f * a[q], &sa, &ca);
        __sincosf(0.5f * b[q], &sb2, &cb2);
        sq[q][0] = C2{ca * cb2, -ca * sb2};
        sq[q][1] = C2{sa * sb2, -sa * cb2};
    }
    C2 vl = cmul(cmul(cmul(cmul(sq[0][(lane >> 4) & 1], sq[1][(lane >> 3) & 1]),
                           sq[2][(lane >> 2) & 1]), sq[4][(lane >> 1) & 1]),
                 sq[5][lane & 1]);

    float sr[16], si[16];
#pragma unroll
    for (int r = 0; r < 16; r++) { sr[r] = 0.f; si[r] = 0.f; }
    {
        C2 v00 = cmul(vl, cmul(sq[3][0], sq[6][0])); sr[0] = v00.x; si[0] = v00.y;
        C2 v01 = cmul(vl, cmul(sq[3][0], sq[6][1])); sr[1] = v01.x; si[1] = v01.y;
        C2 v10 = cmul(vl, cmul(sq[3][1], sq[6][0])); sr[8] = v10.x; si[8] = v10.y;
        C2 v11 = cmul(vl, cmul(sq[3][1], sq[6][1])); sr[9] = v11.x; si[9] = v11.y;
    }

    // fused strong blocks
    strong_ll(sr, si, 16, 2, lane);   // i=0: e=q0(L16), nb=q4(L2)
    strong_ll(sr, si, 8, 1, lane);    // i=1: e=q1(L8),  nb=q5(L1)
    strong_lr1(sr, si, 4, lane);      // i=2: e=q2(L4),  nb=q6(R1)

    // update blocks: wires [q3(R8), q4+i, q7(R4), q8(R2)]
    // i=0: q4 = L2
    g1r<8>(sr, si, ldmat(6));  g1l(sr, si, 2, ldmat(7), lane);
    g1r<4>(sr, si, ldmat(8));  g1r<2>(sr, si, ldmat(9));
    cx_rl<8>(sr, si, 2); cx_lr<4>(sr, si, 2, lane); cx_rr<4, 2>(sr, si); cx_rr<2, 8>(sr, si);
    g1r<8>(sr, si, ldmat(10)); g1l(sr, si, 2, ldmat(11), lane);
    g1r<4>(sr, si, ldmat(12)); g1r<2>(sr, si, ldmat(13));
    cx_rr<8, 4>(sr, si); cx_lr<2>(sr, si, 2, lane); cx_rr<4, 8>(sr, si); cx_rl<2>(sr, si, 2);

    // i=1: q5 = L1
    g1r<8>(sr, si, ldmat(14)); g1l(sr, si, 1, ldmat(15), lane);
    g1r<4>(sr, si, ldmat(16)); g1r<2>(sr, si, ldmat(17));
    cx_rl<8>(sr, si, 1); cx_lr<4>(sr, si, 1, lane); cx_rr<4, 2>(sr, si); cx_rr<2, 8>(sr, si);
    g1r<8>(sr, si, ldmat(18)); g1l(sr, si, 1, ldmat(19), lane);
    g1r<4>(sr, si, ldmat(20)); g1r<2>(sr, si, ldmat(21));
    cx_rr<8, 4>(sr, si); cx_lr<2>(sr, si, 1, lane); cx_rr<4, 8>(sr, si); cx_rl<2>(sr, si, 1);

    // i=2: q6 = R1 (fully register-local)
    g1r<8>(sr, si, ldmat(22)); g1r<1>(sr, si, ldmat(23));
    g1r<4>(sr, si, ldmat(24)); g1r<2>(sr, si, ldmat(25));
    cx_rr<8, 1>(sr, si); cx_rr<1, 4>(sr, si); cx_rr<4, 2>(sr, si); cx_rr<2, 8>(sr, si);
    g1r<8>(sr, si, ldmat(26)); g1r<1>(sr, si, ldmat(27));
    g1r<4>(sr, si, ldmat(28)); g1r<2>(sr, si, ldmat(29));
    cx_rr<8, 4>(sr, si); cx_rr<1, 2>(sr, si); cx_rr<4, 8>(sr, si); cx_rr<2, 1>(sr, si);

    // measurements <Z> on q3(R8), q7(R4), q8(R2)
    float m3 = 0.f, m7 = 0.f, m8 = 0.f;
#pragma unroll
    for (int r = 0; r < 16; r++) {
        float p = fmaf(sr[r], sr[r], si[r] * si[r]);
        m3 += (r & 8) ? -p : p;
        m7 += (r & 4) ? -p : p;
        m8 += (r & 2) ? -p : p;
    }
#pragma unroll
    for (int o = 16; o; o >>= 1) {
        m3 += __shfl_xor_sync(0xFFFFFFFFu, m3, o);
        m7 += __shfl_xor_sync(0xFFFFFFFFu, m7, o);
        m8 += __shfl_xor_sync(0xFFFFFFFFu, m8, o);
    }

    // ---- Phase 3: classifier head ------------------------------------------
    float in5[5] = {a[3], b[3], m3, m7, m8};

    float u0 = 0.f, u1 = 0.f;
#pragma unroll
    for (int r = 0; r < 4; r++) {
        int d = lane + 32 * r;
        float h = __ldg(bu1 + d);
#pragma unroll
        for (int k = 0; k < 5; k++) h = fmaf(in5[k], __ldg(Wu1 + k * 128 + d), h);
        h = lrelu(h);
        float2 w2 = __ldg((const float2*)(Wu2 + d * 2));
        u0 = fmaf(h, w2.x, u0);
        u1 = fmaf(h, w2.y, u1);
    }
#pragma unroll
    for (int o = 16; o; o >>= 1) {
        u0 += __shfl_xor_sync(0xFFFFFFFFu, u0, o);
        u1 += __shfl_xor_sync(0xFFFFFFFFu, u1, o);
    }
    float h0 = in5[0] + u0 + __ldg(bu2);
    float h1 = in5[1] + u1 + __ldg(bu2 + 1);

    float mu = 0.5f * (h0 + h1);
    float d0 = h0 - mu, d1 = h1 - mu;
    float var = 0.5f * (d0 * d0 + d1 * d1);
    float inv = rsqrtf(var + 1e-5f);
    h0 = d0 * inv * __ldg(ln_g) + __ldg(ln_b);
    h1 = d1 * inv * __ldg(ln_g + 1) + __ldg(ln_b + 1);

    float av[4];
#pragma unroll
    for (int r = 0; r < 4; r++) {
        int d = lane + 32 * r;
        av[r] = lrelu(fmaf(h0, __ldg(Wf1 + d), fmaf(h1, __ldg(Wf1 + 128 + d), __ldg(bf1 + d))));
    }

    float bv[4];
#pragma unroll
    for (int r = 0; r < 4; r++) bv[r] = __ldg(bf2 + lane + 32 * r);
    for (int k = 0; k < 128; k++) {
        float ak = __shfl_sync(0xFFFFFFFFu, av[k >> 5], k & 31);
        const float* row = Wf2 + k * 128;
#pragma unroll
        for (int r = 0; r < 4; r++) bv[r] = fmaf(ak, __ldg(row + lane + 32 * r), bv[r]);
    }

    float o0 = 0.f, o1 = 0.f;
#pragma unroll
    for (int r = 0; r < 4; r++) {
        int d = lane + 32 * r;
        float t = lrelu(bv[r]);
        float2 w3 = __ldg((const float2*)(Wf3 + d * 2));
        o0 = fmaf(t, w3.x, o0);
        o1 = fmaf(t, w3.y, o1);
    }
#pragma unroll
    for (int o = 16; o; o >>= 1) {
        o0 += __shfl_xor_sync(0xFFFFFFFFu, o0, o);
        o1 += __shfl_xor_sync(0xFFFFFFFFu, o1, o);
    }
    if (lane == 0) {
        o0 += __ldg(bf3);
        o1 += __ldg(bf3 + 1);
        out[n * 2 + 0] = 1.f / (1.f + __expf(-o0));
        out[n * 2 + 1] = 1.f / (1.f + __expf(-o1));
    }
}

// ---------------------------------------------------------------------------
extern "C" void kernel_launch(void* const* d_in, const int* in_sizes, int n_in,
                              void* d_out, int out_size)
{
    (void)in_sizes; (void)n_in; (void)out_size;
    const float* x_ue      = (const float*)d_in[0];
    const float* x_ap      = (const float*)d_in[1];
    const float* edge_attr = (const float*)d_in[2];
    const int*   edge_src  = (const int*)  d_in[3];
    const float* Wn1u = (const float*)d_in[5];
    const float* bn1u = (const float*)d_in[6];
    const float* Wn2u = (const float*)d_in[7];
    const float* bn2u = (const float*)d_in[8];
    const float* Wn1a = (const float*)d_in[9];
    const float* bn1a = (const float*)d_in[10];
    const float* Wn2a = (const float*)d_in[11];
    const float* bn2a = (const float*)d_in[12];
    const float* We1  = (const float*)d_in[13];
    const float* be1  = (const float*)d_in[14];
    const float* We2  = (const float*)d_in[15];
    const float* be2  = (const float*)d_in[16];
    const float* strong = (const float*)d_in[17];
    const float* inits  = (const float*)d_in[18];
    const float* update = (const float*)d_in[19];
    const float* Wu1  = (const float*)d_in[20];
    const float* bu1  = (const float*)d_in[21];
    const float* Wu2  = (const float*)d_in[22];
    const float* bu2  = (const float*)d_in[23];
    const float* ln_g = (const float*)d_in[24];
    const float* ln_b = (const float*)d_in[25];
    const float* Wf1  = (const float*)d_in[26];
    const float* bf1  = (const float*)d_in[27];
    const float* Wf2  = (const float*)d_in[28];
    const float* bf2  = (const float*)d_in[29];
    const float* Wf3  = (const float*)d_in[30];
    const float* bf3  = (const float*)d_in[31];

    mats_kernel<<<1, 32>>>(strong, inits, update);

    mega_kernel<<<N_UE / 8, 256>>>(x_ue, x_ap, edge_attr, edge_src,
                                   Wn1u, bn1u, Wn2u, bn2u,
                                   Wn1a, bn1a, Wn2a, bn2a,
                                   We1, be1, We2, be2,
                                   Wu1, bu1, Wu2, bu2,
                                   ln_g, ln_b, Wf1, bf1, Wf2, bf2, Wf3, bf3,
                                   (float*)d_out);
}